// round 9
// baseline (speedup 1.0000x reference)
#include <cuda_runtime.h>
#include <math.h>

#define NB 8
#define NC 21
#define HW 4096
#define CF 768
#define NJ 42   // NC * 2

// ---------------- scratch (__device__ globals; no allocation allowed) ----------------
__device__ float g_featT[NB * HW * CF];   // [n][m][d]
__device__ float g_fpart[24 * NB * HW];   // per-d-tile partial sumsq
__device__ float g_fnorm[NB * HW];        // ||feat[n,m]||
__device__ int   g_pcls[NB * HW];         // class of pixel if valid else -1
__device__ int   g_list[NB * NC * HW];    // valid pixel indices per (n,c), ascending
__device__ int   g_cnt[NB * NC];
__device__ float g_cent[NB * NJ * CF];    // [n][c*2+k][d]
__device__ float g_cnorm[NB * NJ];
__device__ float g_D[NB * NJ * HW];       // [n][j][m] = centers[j] . feat[m]
__device__ float g_Kmat[NB * NC * HW * 2];// [n][c][m][k]
__device__ float g_r[NB * NC * HW];
__device__ float g_cv[NB * NJ];           // sinkhorn column scalings

// packed f32x2 FMA (FFMA2): d = a*b + d, lane-wise on 2 packed floats
#define FMA_F32X2(d, a, b) \
    asm("fma.rn.f32x2 %0, %1, %2, %0;" : "+l"(d) : "l"(a), "l"(b))

// ---------------- 1. transpose feature + per-column partial sumsq ----------------
__global__ void k_transpose(const float* __restrict__ feat) {
    __shared__ float tile[32][33];
    __shared__ float colp[8][33];
    int n = blockIdx.z;
    int d0 = blockIdx.y * 32, m0 = blockIdx.x * 32;
    int tx = threadIdx.x, ty = threadIdx.y;
    float acc = 0.f;
    for (int i = ty; i < 32; i += 8) {
        float v = feat[(n * CF + d0 + i) * HW + m0 + tx];
        tile[i][tx] = v;
        acc += v * v;
    }
    colp[ty][tx] = acc;
    __syncthreads();
    for (int i = ty; i < 32; i += 8)
        g_featT[((size_t)n * HW + m0 + i) * CF + d0 + tx] = tile[tx][i];
    if (ty == 0) {
        float s = 0.f;
        #pragma unroll
        for (int r = 0; r < 8; r++) s += colp[r][tx];
        g_fpart[blockIdx.y * (NB * HW) + n * HW + m0 + tx] = s;
    }
}

// ---------------- 2. finalize feature norms (deterministic 24-way sum) ----------------
__global__ void k_fnfin() {
    int idx = blockIdx.x * blockDim.x + threadIdx.x;
    if (idx >= NB * HW) return;
    float s = 0.f;
    #pragma unroll
    for (int k = 0; k < 24; k++) s += g_fpart[k * (NB * HW) + idx];
    g_fnorm[idx] = sqrtf(s);
}

// ---------------- 3a. per-pixel argmax class, full-chip elementwise ----------------
__global__ void k_argmax(const float* __restrict__ cam, const float* __restrict__ label) {
    int idx = blockIdx.x * blockDim.x + threadIdx.x;
    if (idx >= NB * HW) return;
    int n = idx >> 12, m = idx & (HW - 1);
    const float* cp = cam + (size_t)n * NC * HW + m;
    float best = cp[0];
    int bi = 0;
    #pragma unroll
    for (int c = 1; c < NC; c++) {
        float v = cp[c * HW];
        if (v > best) { best = v; bi = c; }   // first max on ties
    }
    g_pcls[idx] = (label[n * NC + bi] > 0.f) ? bi : -1;
}

// ---- 3b. ordered compaction, two-phase (count/scan/write), block per n, warp per class ----
__global__ void __launch_bounds__(672) k_lists() {
    __shared__ int sw[128 * 33];   // swizzled classes: sw[(m&127)*33 + (m>>7)]
    int n = blockIdx.x, t = threadIdx.x;
    for (int m = t; m < HW; m += 672)
        sw[(m & 127) * 33 + (m >> 7)] = g_pcls[n * HW + m];
    __syncthreads();
    int w = t >> 5, lane = t & 31;   // warp w = class, lane owns segment [lane*128, lane*128+128)
    // phase 1: count matches in my segment (conflict-free: bank = (i + lane) & 31)
    int cnt = 0;
    #pragma unroll 8
    for (int i = 0; i < 128; i++) cnt += (sw[i * 33 + lane] == w);
    // exclusive warp scan -> my output offset
    int off = cnt;
    #pragma unroll
    for (int o = 1; o < 32; o <<= 1) {
        int vv = __shfl_up_sync(0xffffffffu, off, o);
        if (lane >= o) off += vv;
    }
    int total = __shfl_sync(0xffffffffu, off, 31);
    off -= cnt;                      // exclusive
    // phase 2: write my matches at [off ...): segment-major order == ascending m
    int* lst = g_list + ((size_t)n * NC + w) * HW;
    for (int i = 0; i < 128; i++) {
        if (sw[i * 33 + lane] == w) lst[off++] = lane * 128 + i;
    }
    if (lane == 31) g_cnt[n * NC + w] = total;
}

// ---- 4. k-means: 8 warps, 2-px ILP, float4 loads, pipelined, convergence early-exit ----
#define KW 8   // warps per kmeans block

#define LOADPAIR(VA, VB, HAS, PI) {                                   \
    int _m0 = lst[PI];                                                \
    HAS = (PI + 1 < cnt);                                             \
    int _m1 = HAS ? lst[(PI) + 1] : _m0;                              \
    const float4* _fa = (const float4*)(fbase + (size_t)_m0 * CF) + lane; \
    const float4* _fb = (const float4*)(fbase + (size_t)_m1 * CF) + lane; \
    _Pragma("unroll")                                                 \
    for (int _j = 0; _j < 6; _j++) {                                  \
        VA[_j] = _fa[_j * 32];                                        \
        VB[_j] = _fb[_j * 32];                                        \
    } }

#define DOTPAIR(VA, VB) {                                             \
    d0a = 0.f; d1a = 0.f; d0b = 0.f; d1b = 0.f;                       \
    _Pragma("unroll")                                                 \
    for (int _j = 0; _j < 6; _j++) {                                  \
        float4 _c0 = cen4[lane + _j * 32];                            \
        float4 _c1 = cen4[48 * 4 + lane + _j * 32];                   \
        d0a += VA[_j].x * _c0.x + VA[_j].y * _c0.y                    \
             + VA[_j].z * _c0.z + VA[_j].w * _c0.w;                   \
        d1a += VA[_j].x * _c1.x + VA[_j].y * _c1.y                    \
             + VA[_j].z * _c1.z + VA[_j].w * _c1.w;                   \
        d0b += VB[_j].x * _c0.x + VB[_j].y * _c0.y                    \
             + VB[_j].z * _c0.z + VB[_j].w * _c0.w;                   \
        d1b += VB[_j].x * _c1.x + VB[_j].y * _c1.y                    \
             + VB[_j].z * _c1.z + VB[_j].w * _c1.w;                   \
    } }

#define FINPAIR(VA, VB, HAS, PI) {                                    \
    _Pragma("unroll")                                                 \
    for (int _o = 16; _o; _o >>= 1) {                                 \
        d0a += __shfl_xor_sync(0xffffffffu, d0a, _o);                 \
        d1a += __shfl_xor_sync(0xffffffffu, d1a, _o);                 \
        d0b += __shfl_xor_sync(0xffffffffu, d0b, _o);                 \
        d1b += __shfl_xor_sync(0xffffffffu, d1b, _o);                 \
    }                                                                 \
    int _aa = (d1a * inv1 > d0a * inv0) ? 1 : 0;                      \
    int _ab = (d1b * inv1 > d0b * inv0) ? 1 : 0;                      \
    if (!lane) {                                                      \
        if (iter > 0) mychg += (sprev[PI] != _aa)                     \
                             + (HAS ? (sprev[(PI) + 1] != _ab) : 0);  \
        sprev[PI] = (unsigned char)_aa;                               \
        if (HAS) sprev[(PI) + 1] = (unsigned char)_ab;                \
    }                                                                 \
    float _w0a = _aa ? 0.f : 1.f, _w1a = _aa ? 1.f : 0.f;             \
    float _w0b = 0.f, _w1b = 0.f;                                     \
    if (HAS) { _w0b = _ab ? 0.f : 1.f; _w1b = _ab ? 1.f : 0.f; }      \
    _Pragma("unroll")                                                 \
    for (int _j = 0; _j < 6; _j++) {                                  \
        acc0[_j].x = fmaf(_w0a, VA[_j].x, fmaf(_w0b, VB[_j].x, acc0[_j].x)); \
        acc0[_j].y = fmaf(_w0a, VA[_j].y, fmaf(_w0b, VB[_j].y, acc0[_j].y)); \
        acc0[_j].z = fmaf(_w0a, VA[_j].z, fmaf(_w0b, VB[_j].z, acc0[_j].z)); \
        acc0[_j].w = fmaf(_w0a, VA[_j].w, fmaf(_w0b, VB[_j].w, acc0[_j].w)); \
        acc1[_j].x = fmaf(_w1a, VA[_j].x, fmaf(_w1b, VB[_j].x, acc1[_j].x)); \
        acc1[_j].y = fmaf(_w1a, VA[_j].y, fmaf(_w1b, VB[_j].y, acc1[_j].y)); \
        acc1[_j].z = fmaf(_w1a, VA[_j].z, fmaf(_w1b, VB[_j].z, acc1[_j].z)); \
        acc1[_j].w = fmaf(_w1a, VA[_j].w, fmaf(_w1b, VB[_j].w, acc1[_j].w)); \
    }                                                                 \
    myc0 += (1 - _aa) + (HAS ? (1 - _ab) : 0);                        \
    myc1 += _aa + (HAS ? _ab : 0); }

__global__ void __launch_bounds__(32 * KW) k_kmeans() {
    extern __shared__ float buf[];
    float* cen  = buf;            // [2][CF]
    float* part = buf + 2 * CF;   // [KW][2][CF]
    float4* cen4 = (float4*)cen;
    __shared__ unsigned char sprev[HW];
    __shared__ int   pcnt[KW][2];
    __shared__ int   pchg[KW];
    __shared__ float inv_s[2];
    __shared__ int   cnts[2], schg;
    int bc = blockIdx.x;
    int n = bc / NC;
    int t = threadIdx.x, wid = t >> 5, lane = t & 31;
    int cnt = g_cnt[bc];
    float* gc = g_cent + (size_t)bc * 2 * CF;
    if (cnt < 2) {   // reference: centers forced to zero
        for (int i = t; i < 2 * CF; i += 32 * KW) gc[i] = 0.f;
        if (t < 2) g_cnorm[bc * 2 + t] = 0.f;
        return;
    }
    const int* lst = g_list + (size_t)bc * HW;
    const float* fbase = g_featT + (size_t)n * HW * CF;
    int i0 = lst[0], i1 = lst[1];
    for (int d = t; d < CF; d += 32 * KW) {
        cen[d]      = fbase[(size_t)i0 * CF + d];
        cen[CF + d] = fbase[(size_t)i1 * CF + d];
    }
    __syncthreads();

    for (int iter = 0; iter < 10; iter++) {
        if (wid < 2) {   // center inverse norms
            float s = 0.f;
            for (int d = lane; d < CF; d += 32) { float v = cen[wid * CF + d]; s += v * v; }
            #pragma unroll
            for (int o = 16; o; o >>= 1) s += __shfl_xor_sync(0xffffffffu, s, o);
            if (!lane) inv_s[wid] = 1.f / fmaxf(sqrtf(s), 1e-8f);
        }
        __syncthreads();
        float inv0 = inv_s[0], inv1 = inv_s[1];
        float4 acc0[6], acc1[6];
        #pragma unroll
        for (int j = 0; j < 6; j++) {
            acc0[j] = make_float4(0.f, 0.f, 0.f, 0.f);
            acc1[j] = make_float4(0.f, 0.f, 0.f, 0.f);
        }
        int myc0 = 0, myc1 = 0, mychg = 0;

        // software-pipelined 2-pixel steps with next-pair prefetch
        float4 vax[6], vbx[6], vay[6], vby[6];
        float d0a, d1a, d0b, d1b;
        int hasx = 0, hasy = 0;
        int pi = wid * 2;
        if (pi < cnt) LOADPAIR(vax, vbx, hasx, pi);
        while (pi < cnt) {
            int pj = pi + 2 * KW;
            if (pj < cnt) LOADPAIR(vay, vby, hasy, pj);
            DOTPAIR(vax, vbx);
            FINPAIR(vax, vbx, hasx, pi);
            pi = pj;
            if (pi >= cnt) break;
            pj = pi + 2 * KW;
            if (pj < cnt) LOADPAIR(vax, vbx, hasx, pj);
            DOTPAIR(vay, vby);
            FINPAIR(vay, vby, hasy, pi);
            pi = pj;
        }

        float4* p0 = (float4*)&part[(wid * 2 + 0) * CF];
        float4* p1 = (float4*)&part[(wid * 2 + 1) * CF];
        #pragma unroll
        for (int j = 0; j < 6; j++) {   // one smem dump per iteration
            p0[lane + j * 32] = acc0[j];
            p1[lane + j * 32] = acc1[j];
        }
        if (!lane) { pcnt[wid][0] = myc0; pcnt[wid][1] = myc1; pchg[wid] = mychg; }
        __syncthreads();
        if (t < 2) {
            int s = 0;
            #pragma unroll
            for (int w2 = 0; w2 < KW; w2++) s += pcnt[w2][t];
            cnts[t] = s;
        }
        if (t == 2) {
            int s = 0;
            #pragma unroll
            for (int w2 = 0; w2 < KW; w2++) s += pchg[w2];
            schg = s;
        }
        __syncthreads();
        float div0 = 1.f / fmaxf((float)cnts[0], 1.f);
        float div1 = 1.f / fmaxf((float)cnts[1], 1.f);
        for (int d = t; d < CF; d += 32 * KW) {
            float s0 = 0.f, s1 = 0.f;
            #pragma unroll
            for (int w2 = 0; w2 < KW; w2++) {
                s0 += part[(w2 * 2) * CF + d];
                s1 += part[(w2 * 2 + 1) * CF + d];
            }
            cen[d] = s0 * div0;
            cen[CF + d] = s1 * div1;
        }
        __syncthreads();
        // assignments identical to previous iteration -> fixed point; rest are no-ops
        if (iter > 0 && schg == 0) break;
    }
    for (int d = t; d < CF; d += 32 * KW) { gc[d] = cen[d]; gc[CF + d] = cen[CF + d]; }
    if (wid < 2) {
        float s = 0.f;
        for (int d = lane; d < CF; d += 32) { float v = cen[wid * CF + d]; s += v * v; }
        #pragma unroll
        for (int o = 16; o; o >>= 1) s += __shfl_xor_sync(0xffffffffu, s, o);
        if (!lane) g_cnorm[bc * 2 + wid] = sqrtf(s);
    }
}

// ---- 5. GEMM via packed f32x2 FMA, 256 threads: D[n][j][m] = centers[n][j].feat[n][m] ----
#define GT 48   // k-tile
__global__ void __launch_bounds__(256) k_gemm(const float* __restrict__ feat) {
    extern __shared__ float sm[];
    float* fS = sm;                                            // [GT][256]
    unsigned long long* cS2 = (unsigned long long*)(sm + GT * 256);  // [NJ][GT]
    int n = blockIdx.y, m0 = blockIdx.x * 256;
    int t = threadIdx.x;
    int p = t & 127, g = t >> 7;    // g = j-group (warp-uniform)
    unsigned long long acc[21];
    #pragma unroll
    for (int j = 0; j < 21; j++) acc[j] = 0ull;

    for (int k0 = 0; k0 < CF; k0 += GT) {
        __syncthreads();
        for (int idx = t; idx < GT * 64; idx += 256) {
            int dd = idx >> 6, c4 = idx & 63;
            float4 v = *(const float4*)&feat[((size_t)(n * CF + k0 + dd)) * HW + m0 + c4 * 4];
            *(float4*)&fS[dd * 256 + c4 * 4] = v;
        }
        for (int idx = t; idx < NJ * GT; idx += 256) {
            int j = idx / GT, dd = idx % GT;
            float v = g_cent[((size_t)n * NJ + j) * CF + k0 + dd];
            float2 d2 = make_float2(v, v);
            cS2[j * GT + dd] = *(unsigned long long*)&d2;
        }
        __syncthreads();
        #pragma unroll 4
        for (int dd = 0; dd < GT; dd += 2) {
            unsigned long long a0 = *(const unsigned long long*)&fS[dd * 256 + 2 * p];
            unsigned long long a1 = *(const unsigned long long*)&fS[(dd + 1) * 256 + 2 * p];
            #pragma unroll
            for (int j = 0; j < 21; j++) {
                ulonglong2 c2 = *(const ulonglong2*)&cS2[(g * 21 + j) * GT + dd];
                FMA_F32X2(acc[j], a0, c2.x);
                FMA_F32X2(acc[j], a1, c2.y);
            }
        }
    }
    #pragma unroll
    for (int j = 0; j < 21; j++) {
        float* dp = g_D + ((size_t)n * NJ + g * 21 + j) * HW + m0;
        *(float2*)&dp[2 * p] = *(float2*)&acc[j];
    }
}

// ---------------- 6. fused cam + per-map max-normalize + Sinkhorn K matrix ----------------
__global__ void __launch_bounds__(512) k_camkmat(const float* __restrict__ label,
                                                 float* __restrict__ out) {
    __shared__ float scam[HW];
    __shared__ float red[512];
    int bc = blockIdx.x, n = bc / NC, c = bc % NC, t = threadIdx.x;
    int cnt = g_cnt[bc];
    float lab = label[bc];
    float inv_cn0 = 1.f / fmaxf(g_cnorm[n * NJ + 2 * c], 1e-8f);
    float inv_cn1 = 1.f / fmaxf(g_cnorm[n * NJ + 2 * c + 1], 1e-8f);
    float ik0 = 1.f / (g_cnorm[n * NJ + c] + 1e-5f);         // kmat quirk: j = k*21 + c
    float ik1 = 1.f / (g_cnorm[n * NJ + NC + c] + 1e-5f);
    const float* D0  = g_D + ((size_t)n * NJ + 2 * c) * HW;
    const float* D1  = D0 + HW;
    const float* Dk0 = g_D + ((size_t)n * NJ + c) * HW;
    const float* Dk1 = g_D + ((size_t)n * NJ + NC + c) * HW;
    float2* Km2 = (float2*)(g_Kmat + (size_t)bc * HW * 2);
    float mx = -INFINITY;
    for (int m = t; m < HW; m += 512) {
        float fn = g_fnorm[n * HW + m];
        float camv = 0.f;
        if (cnt >= 2) {
            float fi = 1.f / fmaxf(fn, 1e-8f);
            camv = 0.5f * (D0[m] * inv_cn0 + D1[m] * inv_cn1) * fi * lab;
        }
        scam[m] = camv;
        mx = fmaxf(mx, camv);
        float fk = 1.f / (fn + 1e-5f);
        float2 kk;
        kk.x = __expf((Dk0[m] * fk * ik0 - 1.f) * 10.f);
        kk.y = __expf((Dk1[m] * fk * ik1 - 1.f) * 10.f);
        Km2[m] = kk;
    }
    red[t] = mx;
    __syncthreads();
    for (int s = 256; s; s >>= 1) { if (t < s) red[t] = fmaxf(red[t], red[t + s]); __syncthreads(); }
    float inv = 1.f / (red[0] + 1e-5f);
    for (int m = t; m < HW; m += 512) out[(size_t)bc * HW + m] = scam[m] * inv;
}

// ---- 7. Sinkhorn, fused r+c single pass per iteration, faithful early stop, block per n ----
__global__ void __launch_bounds__(1024) k_sinkhorn() {
    __shared__ float cv[NJ];
    __shared__ float spart[NC][32][2];
    __shared__ float red[1024];
    __shared__ float errS;
    int n = blockIdx.x, t = threadIdx.x, lane = t & 31, wid = t >> 5;
    const float u = 1.f / (float)HW, v = 0.5f;
    float* rg = g_r + (size_t)n * NC * HW;
    const float4* Km4 = (const float4*)(g_Kmat + (size_t)n * NC * HW * 2);
    if (t < NJ) cv[t] = 1.f;
    for (int i = t; i < NC * HW; i += 1024) rg[i] = 1.f;
    __syncthreads();

    for (int it = 0; it < 100; it++) {
        float errp = 0.f;
        // fused pass: r = u/(K@c_old) and per-class partials of K^T@r_new
        for (int c = 0; c < NC; c++) {
            float c0 = cv[2 * c], c1 = cv[2 * c + 1];
            float s0 = 0.f, s1 = 0.f;
            #pragma unroll
            for (int st = 0; st < 2; st++) {
                int i2 = t + (2 * c + st) * 1024;   // class(i2*2) == c for all t
                int i = 2 * i2;
                float4 kk = Km4[i2];
                float rn0 = u / (kk.x * c0 + kk.y * c1);
                float rn1 = u / (kk.z * c0 + kk.w * c1);
                errp += fabsf(rn0 - rg[i]) + fabsf(rn1 - rg[i + 1]);
                rg[i] = rn0; rg[i + 1] = rn1;
                s0 += kk.x * rn0 + kk.z * rn1;
                s1 += kk.y * rn0 + kk.w * rn1;
            }
            #pragma unroll
            for (int o = 16; o; o >>= 1) {
                s0 += __shfl_xor_sync(0xffffffffu, s0, o);
                s1 += __shfl_xor_sync(0xffffffffu, s1, o);
            }
            if (!lane) { spart[c][wid][0] = s0; spart[c][wid][1] = s1; }
        }
        red[t] = errp;
        __syncthreads();
        for (int s = 512; s; s >>= 1) { if (t < s) red[t] += red[t + s]; __syncthreads(); }
        // all pass work done; safe to overwrite cv (deterministic 32-way sum)
        if (t < NJ) {
            int c = t >> 1, k = t & 1;
            float s = 0.f;
            #pragma unroll
            for (int w = 0; w < 32; w++) s += spart[c][w][k];
            cv[t] = v / s;
        }
        if (!t) errS = red[0] / (float)(NC * HW);
        __syncthreads();
        if (errS < 0.01f) break;
    }
    if (t < NJ) g_cv[n * NJ + t] = cv[t];
}

// ---------------- 8. T output: full-chip elementwise r*c*K, block per (n,c) ----------------
__global__ void __launch_bounds__(512) k_tout(float* __restrict__ Tout) {
    int bc = blockIdx.x, n = bc / NC, c = bc % NC, t = threadIdx.x;
    const float2* Km2 = (const float2*)g_Kmat + (size_t)bc * HW;
    const float* rp = g_r + (size_t)bc * HW;
    float cv0 = g_cv[n * NJ + 2 * c], cv1 = g_cv[n * NJ + 2 * c + 1];
    float* T0 = Tout + (size_t)bc * 2 * HW;   // [n][c][k=0][m]
    float* T1 = T0 + HW;                      // [n][c][k=1][m]
    for (int m = t; m < HW; m += 512) {
        float2 kk = Km2[m];
        float r = rp[m];
        T0[m] = r * cv0 * kk.x;
        T1[m] = r * cv1 * kk.y;
    }
}

// ---------------- launcher: fork seed path (argmax+lists) alongside transpose ----------------
extern "C" void kernel_launch(void* const* d_in, const int* in_sizes, int n_in,
                              void* d_out, int out_size) {
    const float* norm_cam = (const float*)d_in[0];   // [8,21,64,64]
    const float* label    = (const float*)d_in[1];   // [8,21,1,1]
    const float* feature  = (const float*)d_in[2];   // [8,768,64,64]
    float* out  = (float*)d_out;                     // [8,21,64,64]
    float* Tout = out + NB * NC * HW;                // [8,21,2,64,64]

    const int KMEANS_SMEM = (2 * CF + KW * 2 * CF) * sizeof(float);      // 55296 B
    const int GEMM_SMEM   = GT * 256 * 4 + NJ * GT * 8;                  // 65280 B
    cudaFuncSetAttribute(k_kmeans, cudaFuncAttributeMaxDynamicSharedMemorySize, KMEANS_SMEM);
    cudaFuncSetAttribute(k_gemm,   cudaFuncAttributeMaxDynamicSharedMemorySize, GEMM_SMEM);

    cudaStream_t s2;
    cudaEvent_t eFork, eJoin;
    cudaStreamCreateWithFlags(&s2, cudaStreamNonBlocking);
    cudaEventCreateWithFlags(&eFork, cudaEventDisableTiming);
    cudaEventCreateWithFlags(&eJoin, cudaEventDisableTiming);

    // fork: seed path (argmax -> lists) concurrent with feature transpose
    cudaEventRecord(eFork, 0);
    cudaStreamWaitEvent(s2, eFork, 0);
    k_argmax <<<(NB * HW + 255) / 256, 256, 0, s2>>>(norm_cam, label);
    k_lists  <<<NB, 672, 0, s2>>>();
    cudaEventRecord(eJoin, s2);

    k_transpose<<<dim3(HW / 32, CF / 32, NB), dim3(32, 8)>>>(feature);
    k_fnfin   <<<(NB * HW + 255) / 256, 256>>>();

    cudaStreamWaitEvent(0, eJoin, 0);    // join before kmeans
    k_kmeans  <<<NB * NC, 32 * KW, KMEANS_SMEM>>>();
    k_gemm    <<<dim3(HW / 256, NB), 256, GEMM_SMEM>>>(feature);
    k_camkmat <<<NB * NC, 512>>>(label, out);
    k_sinkhorn<<<NB, 1024>>>();
    k_tout    <<<NB * NC, 512>>>(Tout);

    cudaEventDestroy(eFork);
    cudaEventDestroy(eJoin);
    cudaStreamDestroy(s2);
}

// round 10
// speedup vs baseline: 1.1498x; 1.1498x over previous
#include <cuda_runtime.h>
#include <math.h>

#define NB 8
#define NC 21
#define HW 4096
#define CF 768
#define NJ 42   // NC * 2

// ---------------- scratch (__device__ globals; no allocation allowed) ----------------
__device__ float g_featT[NB * HW * CF];   // [n][m][d]
__device__ float g_fpart[24 * NB * HW];   // per-d-tile partial sumsq
__device__ float g_fnorm[NB * HW];        // ||feat[n,m]||
__device__ int   g_pcls[NB * HW];         // class of pixel if valid else -1
__device__ int   g_list[NB * NC * HW];    // valid pixel indices per (n,c), ascending
__device__ int   g_cnt[NB * NC];
__device__ float g_cent[NB * NJ * CF];    // [n][c*2+k][d]
__device__ float g_cnorm[NB * NJ];
__device__ float g_D[NB * NJ * HW];       // [n][j][m] = centers[j] . feat[m]
__device__ float g_Kmat[NB * NC * HW * 2];// [n][c][m][k]
__device__ float g_r[NB * NC * HW];
__device__ float g_cv[NB * NJ];           // sinkhorn column scalings

// packed f32x2 FMA (FFMA2): d = a*b + d, lane-wise on 2 packed floats
#define FMA_F32X2(d, a, b) \
    asm("fma.rn.f32x2 %0, %1, %2, %0;" : "+l"(d) : "l"(a), "l"(b))

// ---- 1. transpose feature (float4 both sides) + per-column partial sumsq ----
__global__ void __launch_bounds__(256) k_transpose(const float* __restrict__ feat) {
    __shared__ float tile[32][129];
    int n = blockIdx.z;
    int d0 = blockIdx.y * 32, m0 = blockIdx.x * 128;
    int t = threadIdx.x;
    // load: 32 d x 128 m, LDG.128 along m (512B contiguous per warp)
    #pragma unroll
    for (int i = 0; i < 4; i++) {
        int li = t + i * 256;
        int r = li >> 5, c4 = li & 31;
        float4 v = *(const float4*)&feat[((size_t)(n * CF + d0 + r)) * HW + m0 + c4 * 4];
        tile[r][c4 * 4 + 0] = v.x;
        tile[r][c4 * 4 + 1] = v.y;
        tile[r][c4 * 4 + 2] = v.z;
        tile[r][c4 * 4 + 3] = v.w;
    }
    __syncthreads();
    // write: STG.128 along d (warp = 4 m-rows x 8 d4 = 4x128B segments);
    // conflict-free reads: bank = (4*d4 + k + m) & 31 distinct across lanes
    #pragma unroll
    for (int i = 0; i < 4; i++) {
        int li = t + i * 256;
        int m = li >> 3, d4 = li & 7;
        float4 v;
        v.x = tile[d4 * 4 + 0][m];
        v.y = tile[d4 * 4 + 1][m];
        v.z = tile[d4 * 4 + 2][m];
        v.w = tile[d4 * 4 + 3][m];
        *(float4*)&g_featT[((size_t)(n * HW + m0 + m)) * CF + d0 + d4 * 4] = v;
        float ss = v.x * v.x + v.y * v.y + v.z * v.z + v.w * v.w;
        #pragma unroll
        for (int o = 1; o < 8; o <<= 1) ss += __shfl_xor_sync(0xffffffffu, ss, o);
        if (d4 == 0) g_fpart[blockIdx.y * (NB * HW) + n * HW + m0 + m] = ss;
    }
}

// ---------------- 2. finalize feature norms (deterministic 24-way sum) ----------------
__global__ void k_fnfin() {
    int idx = blockIdx.x * blockDim.x + threadIdx.x;
    if (idx >= NB * HW) return;
    float s = 0.f;
    #pragma unroll
    for (int k = 0; k < 24; k++) s += g_fpart[k * (NB * HW) + idx];
    g_fnorm[idx] = sqrtf(s);
}

// ---------------- 3a. per-pixel argmax class, full-chip elementwise ----------------
__global__ void k_argmax(const float* __restrict__ cam, const float* __restrict__ label) {
    int idx = blockIdx.x * blockDim.x + threadIdx.x;
    if (idx >= NB * HW) return;
    int n = idx >> 12, m = idx & (HW - 1);
    const float* cp = cam + (size_t)n * NC * HW + m;
    float best = cp[0];
    int bi = 0;
    #pragma unroll
    for (int c = 1; c < NC; c++) {
        float v = cp[c * HW];
        if (v > best) { best = v; bi = c; }   // first max on ties
    }
    g_pcls[idx] = (label[n * NC + bi] > 0.f) ? bi : -1;
}

// ---- 3b. ordered compaction, two-phase (count/scan/write), block per n, warp per class ----
__global__ void __launch_bounds__(672) k_lists() {
    __shared__ int sw[128 * 33];   // swizzled classes: sw[(m&127)*33 + (m>>7)]
    int n = blockIdx.x, t = threadIdx.x;
    for (int m = t; m < HW; m += 672)
        sw[(m & 127) * 33 + (m >> 7)] = g_pcls[n * HW + m];
    __syncthreads();
    int w = t >> 5, lane = t & 31;   // warp w = class, lane owns segment [lane*128, lane*128+128)
    int cnt = 0;
    #pragma unroll 8
    for (int i = 0; i < 128; i++) cnt += (sw[i * 33 + lane] == w);
    int off = cnt;
    #pragma unroll
    for (int o = 1; o < 32; o <<= 1) {
        int vv = __shfl_up_sync(0xffffffffu, off, o);
        if (lane >= o) off += vv;
    }
    int total = __shfl_sync(0xffffffffu, off, 31);
    off -= cnt;                      // exclusive
    int* lst = g_list + ((size_t)n * NC + w) * HW;
    for (int i = 0; i < 128; i++) {
        if (sw[i * 33 + lane] == w) lst[off++] = lane * 128 + i;
    }
    if (lane == 31) g_cnt[n * NC + w] = total;
}

// ---- 4. k-means: 8 warps, 2-px ILP, float4 loads, pipelined, convergence early-exit ----
#define KW 8   // warps per kmeans block

#define LOADPAIR(VA, VB, HAS, PI) {                                   \
    int _m0 = lst[PI];                                                \
    HAS = (PI + 1 < cnt);                                             \
    int _m1 = HAS ? lst[(PI) + 1] : _m0;                              \
    const float4* _fa = (const float4*)(fbase + (size_t)_m0 * CF) + lane; \
    const float4* _fb = (const float4*)(fbase + (size_t)_m1 * CF) + lane; \
    _Pragma("unroll")                                                 \
    for (int _j = 0; _j < 6; _j++) {                                  \
        VA[_j] = _fa[_j * 32];                                        \
        VB[_j] = _fb[_j * 32];                                        \
    } }

#define DOTPAIR(VA, VB) {                                             \
    d0a = 0.f; d1a = 0.f; d0b = 0.f; d1b = 0.f;                       \
    _Pragma("unroll")                                                 \
    for (int _j = 0; _j < 6; _j++) {                                  \
        float4 _c0 = cen4[lane + _j * 32];                            \
        float4 _c1 = cen4[48 * 4 + lane + _j * 32];                   \
        d0a += VA[_j].x * _c0.x + VA[_j].y * _c0.y                    \
             + VA[_j].z * _c0.z + VA[_j].w * _c0.w;                   \
        d1a += VA[_j].x * _c1.x + VA[_j].y * _c1.y                    \
             + VA[_j].z * _c1.z + VA[_j].w * _c1.w;                   \
        d0b += VB[_j].x * _c0.x + VB[_j].y * _c0.y                    \
             + VB[_j].z * _c0.z + VB[_j].w * _c0.w;                   \
        d1b += VB[_j].x * _c1.x + VB[_j].y * _c1.y                    \
             + VB[_j].z * _c1.z + VB[_j].w * _c1.w;                   \
    } }

#define FINPAIR(VA, VB, HAS, PI) {                                    \
    _Pragma("unroll")                                                 \
    for (int _o = 16; _o; _o >>= 1) {                                 \
        d0a += __shfl_xor_sync(0xffffffffu, d0a, _o);                 \
        d1a += __shfl_xor_sync(0xffffffffu, d1a, _o);                 \
        d0b += __shfl_xor_sync(0xffffffffu, d0b, _o);                 \
        d1b += __shfl_xor_sync(0xffffffffu, d1b, _o);                 \
    }                                                                 \
    int _aa = (d1a * inv1 > d0a * inv0) ? 1 : 0;                      \
    int _ab = (d1b * inv1 > d0b * inv0) ? 1 : 0;                      \
    if (!lane) {                                                      \
        if (iter > 0) mychg += (sprev[PI] != _aa)                     \
                             + (HAS ? (sprev[(PI) + 1] != _ab) : 0);  \
        sprev[PI] = (unsigned char)_aa;                               \
        if (HAS) sprev[(PI) + 1] = (unsigned char)_ab;                \
    }                                                                 \
    float _w0a = _aa ? 0.f : 1.f, _w1a = _aa ? 1.f : 0.f;             \
    float _w0b = 0.f, _w1b = 0.f;                                     \
    if (HAS) { _w0b = _ab ? 0.f : 1.f; _w1b = _ab ? 1.f : 0.f; }      \
    _Pragma("unroll")                                                 \
    for (int _j = 0; _j < 6; _j++) {                                  \
        acc0[_j].x = fmaf(_w0a, VA[_j].x, fmaf(_w0b, VB[_j].x, acc0[_j].x)); \
        acc0[_j].y = fmaf(_w0a, VA[_j].y, fmaf(_w0b, VB[_j].y, acc0[_j].y)); \
        acc0[_j].z = fmaf(_w0a, VA[_j].z, fmaf(_w0b, VB[_j].z, acc0[_j].z)); \
        acc0[_j].w = fmaf(_w0a, VA[_j].w, fmaf(_w0b, VB[_j].w, acc0[_j].w)); \
        acc1[_j].x = fmaf(_w1a, VA[_j].x, fmaf(_w1b, VB[_j].x, acc1[_j].x)); \
        acc1[_j].y = fmaf(_w1a, VA[_j].y, fmaf(_w1b, VB[_j].y, acc1[_j].y)); \
        acc1[_j].z = fmaf(_w1a, VA[_j].z, fmaf(_w1b, VB[_j].z, acc1[_j].z)); \
        acc1[_j].w = fmaf(_w1a, VA[_j].w, fmaf(_w1b, VB[_j].w, acc1[_j].w)); \
    }                                                                 \
    myc0 += (1 - _aa) + (HAS ? (1 - _ab) : 0);                        \
    myc1 += _aa + (HAS ? _ab : 0); }

__global__ void __launch_bounds__(32 * KW) k_kmeans() {
    extern __shared__ float buf[];
    float* cen  = buf;            // [2][CF]
    float* part = buf + 2 * CF;   // [KW][2][CF]
    float4* cen4 = (float4*)cen;
    __shared__ unsigned char sprev[HW];
    __shared__ int   pcnt[KW][2];
    __shared__ int   pchg[KW];
    __shared__ float inv_s[2];
    __shared__ int   cnts[2], schg;
    int bc = blockIdx.x;
    int n = bc / NC;
    int t = threadIdx.x, wid = t >> 5, lane = t & 31;
    int cnt = g_cnt[bc];
    float* gc = g_cent + (size_t)bc * 2 * CF;
    if (cnt < 2) {   // reference: centers forced to zero
        for (int i = t; i < 2 * CF; i += 32 * KW) gc[i] = 0.f;
        if (t < 2) g_cnorm[bc * 2 + t] = 0.f;
        return;
    }
    const int* lst = g_list + (size_t)bc * HW;
    const float* fbase = g_featT + (size_t)n * HW * CF;
    int i0 = lst[0], i1 = lst[1];
    for (int d = t; d < CF; d += 32 * KW) {
        cen[d]      = fbase[(size_t)i0 * CF + d];
        cen[CF + d] = fbase[(size_t)i1 * CF + d];
    }
    __syncthreads();

    for (int iter = 0; iter < 10; iter++) {
        if (wid < 2) {   // center inverse norms
            float s = 0.f;
            for (int d = lane; d < CF; d += 32) { float v = cen[wid * CF + d]; s += v * v; }
            #pragma unroll
            for (int o = 16; o; o >>= 1) s += __shfl_xor_sync(0xffffffffu, s, o);
            if (!lane) inv_s[wid] = 1.f / fmaxf(sqrtf(s), 1e-8f);
        }
        __syncthreads();
        float inv0 = inv_s[0], inv1 = inv_s[1];
        float4 acc0[6], acc1[6];
        #pragma unroll
        for (int j = 0; j < 6; j++) {
            acc0[j] = make_float4(0.f, 0.f, 0.f, 0.f);
            acc1[j] = make_float4(0.f, 0.f, 0.f, 0.f);
        }
        int myc0 = 0, myc1 = 0, mychg = 0;

        // software-pipelined 2-pixel steps with next-pair prefetch
        float4 vax[6], vbx[6], vay[6], vby[6];
        float d0a, d1a, d0b, d1b;
        int hasx = 0, hasy = 0;
        int pi = wid * 2;
        if (pi < cnt) LOADPAIR(vax, vbx, hasx, pi);
        while (pi < cnt) {
            int pj = pi + 2 * KW;
            if (pj < cnt) LOADPAIR(vay, vby, hasy, pj);
            DOTPAIR(vax, vbx);
            FINPAIR(vax, vbx, hasx, pi);
            pi = pj;
            if (pi >= cnt) break;
            pj = pi + 2 * KW;
            if (pj < cnt) LOADPAIR(vax, vbx, hasx, pj);
            DOTPAIR(vay, vby);
            FINPAIR(vay, vby, hasy, pi);
            pi = pj;
        }

        float4* p0 = (float4*)&part[(wid * 2 + 0) * CF];
        float4* p1 = (float4*)&part[(wid * 2 + 1) * CF];
        #pragma unroll
        for (int j = 0; j < 6; j++) {   // one smem dump per iteration
            p0[lane + j * 32] = acc0[j];
            p1[lane + j * 32] = acc1[j];
        }
        if (!lane) { pcnt[wid][0] = myc0; pcnt[wid][1] = myc1; pchg[wid] = mychg; }
        __syncthreads();
        if (t < 2) {
            int s = 0;
            #pragma unroll
            for (int w2 = 0; w2 < KW; w2++) s += pcnt[w2][t];
            cnts[t] = s;
        }
        if (t == 2) {
            int s = 0;
            #pragma unroll
            for (int w2 = 0; w2 < KW; w2++) s += pchg[w2];
            schg = s;
        }
        __syncthreads();
        float div0 = 1.f / fmaxf((float)cnts[0], 1.f);
        float div1 = 1.f / fmaxf((float)cnts[1], 1.f);
        for (int d = t; d < CF; d += 32 * KW) {
            float s0 = 0.f, s1 = 0.f;
            #pragma unroll
            for (int w2 = 0; w2 < KW; w2++) {
                s0 += part[(w2 * 2) * CF + d];
                s1 += part[(w2 * 2 + 1) * CF + d];
            }
            cen[d] = s0 * div0;
            cen[CF + d] = s1 * div1;
        }
        __syncthreads();
        // assignments identical to previous iteration -> fixed point; rest are no-ops
        if (iter > 0 && schg == 0) break;
    }
    for (int d = t; d < CF; d += 32 * KW) { gc[d] = cen[d]; gc[CF + d] = cen[CF + d]; }
    if (wid < 2) {
        float s = 0.f;
        for (int d = lane; d < CF; d += 32) { float v = cen[wid * CF + d]; s += v * v; }
        #pragma unroll
        for (int o = 16; o; o >>= 1) s += __shfl_xor_sync(0xffffffffu, s, o);
        if (!lane) g_cnorm[bc * 2 + wid] = sqrtf(s);
    }
}

// ---- 5. GEMM via packed f32x2 FMA, 256 threads: D[n][j][m] = centers[n][j].feat[n][m] ----
#define GT 48   // k-tile
__global__ void __launch_bounds__(256) k_gemm(const float* __restrict__ feat) {
    extern __shared__ float sm[];
    float* fS = sm;                                            // [GT][256]
    unsigned long long* cS2 = (unsigned long long*)(sm + GT * 256);  // [NJ][GT]
    int n = blockIdx.y, m0 = blockIdx.x * 256;
    int t = threadIdx.x;
    int p = t & 127, g = t >> 7;    // g = j-group (warp-uniform)
    unsigned long long acc[21];
    #pragma unroll
    for (int j = 0; j < 21; j++) acc[j] = 0ull;

    for (int k0 = 0; k0 < CF; k0 += GT) {
        __syncthreads();
        for (int idx = t; idx < GT * 64; idx += 256) {
            int dd = idx >> 6, c4 = idx & 63;
            float4 v = *(const float4*)&feat[((size_t)(n * CF + k0 + dd)) * HW + m0 + c4 * 4];
            *(float4*)&fS[dd * 256 + c4 * 4] = v;
        }
        for (int idx = t; idx < NJ * GT; idx += 256) {
            int j = idx / GT, dd = idx % GT;
            float v = g_cent[((size_t)n * NJ + j) * CF + k0 + dd];
            float2 d2 = make_float2(v, v);
            cS2[j * GT + dd] = *(unsigned long long*)&d2;
        }
        __syncthreads();
        #pragma unroll 4
        for (int dd = 0; dd < GT; dd += 2) {
            unsigned long long a0 = *(const unsigned long long*)&fS[dd * 256 + 2 * p];
            unsigned long long a1 = *(const unsigned long long*)&fS[(dd + 1) * 256 + 2 * p];
            #pragma unroll
            for (int j = 0; j < 21; j++) {
                ulonglong2 c2 = *(const ulonglong2*)&cS2[(g * 21 + j) * GT + dd];
                FMA_F32X2(acc[j], a0, c2.x);
                FMA_F32X2(acc[j], a1, c2.y);
            }
        }
    }
    #pragma unroll
    for (int j = 0; j < 21; j++) {
        float* dp = g_D + ((size_t)n * NJ + g * 21 + j) * HW + m0;
        *(float2*)&dp[2 * p] = *(float2*)&acc[j];
    }
}

// ---------------- 6. fused cam + per-map max-normalize + Sinkhorn K matrix ----------------
__global__ void __launch_bounds__(512) k_camkmat(const float* __restrict__ label,
                                                 float* __restrict__ out) {
    __shared__ float scam[HW];
    __shared__ float red[512];
    int bc = blockIdx.x, n = bc / NC, c = bc % NC, t = threadIdx.x;
    int cnt = g_cnt[bc];
    float lab = label[bc];
    float inv_cn0 = 1.f / fmaxf(g_cnorm[n * NJ + 2 * c], 1e-8f);
    float inv_cn1 = 1.f / fmaxf(g_cnorm[n * NJ + 2 * c + 1], 1e-8f);
    float ik0 = 1.f / (g_cnorm[n * NJ + c] + 1e-5f);         // kmat quirk: j = k*21 + c
    float ik1 = 1.f / (g_cnorm[n * NJ + NC + c] + 1e-5f);
    const float* D0  = g_D + ((size_t)n * NJ + 2 * c) * HW;
    const float* D1  = D0 + HW;
    const float* Dk0 = g_D + ((size_t)n * NJ + c) * HW;
    const float* Dk1 = g_D + ((size_t)n * NJ + NC + c) * HW;
    float2* Km2 = (float2*)(g_Kmat + (size_t)bc * HW * 2);
    float mx = -INFINITY;
    for (int m = t; m < HW; m += 512) {
        float fn = g_fnorm[n * HW + m];
        float camv = 0.f;
        if (cnt >= 2) {
            float fi = 1.f / fmaxf(fn, 1e-8f);
            camv = 0.5f * (D0[m] * inv_cn0 + D1[m] * inv_cn1) * fi * lab;
        }
        scam[m] = camv;
        mx = fmaxf(mx, camv);
        float fk = 1.f / (fn + 1e-5f);
        float2 kk;
        kk.x = __expf((Dk0[m] * fk * ik0 - 1.f) * 10.f);
        kk.y = __expf((Dk1[m] * fk * ik1 - 1.f) * 10.f);
        Km2[m] = kk;
    }
    red[t] = mx;
    __syncthreads();
    for (int s = 256; s; s >>= 1) { if (t < s) red[t] = fmaxf(red[t], red[t + s]); __syncthreads(); }
    float inv = 1.f / (red[0] + 1e-5f);
    for (int m = t; m < HW; m += 512) out[(size_t)bc * HW + m] = scam[m] * inv;
}

// ---- 7. Sinkhorn, fused r+c single pass per iteration, faithful early stop, block per n ----
__global__ void __launch_bounds__(1024) k_sinkhorn() {
    __shared__ float cv[NJ];
    __shared__ float spart[NC][32][2];
    __shared__ float red[1024];
    __shared__ float errS;
    int n = blockIdx.x, t = threadIdx.x, lane = t & 31, wid = t >> 5;
    const float u = 1.f / (float)HW, v = 0.5f;
    float* rg = g_r + (size_t)n * NC * HW;
    const float4* Km4 = (const float4*)(g_Kmat + (size_t)n * NC * HW * 2);
    if (t < NJ) cv[t] = 1.f;
    for (int i = t; i < NC * HW; i += 1024) rg[i] = 1.f;
    __syncthreads();

    for (int it = 0; it < 100; it++) {
        float errp = 0.f;
        // fused pass: r = u/(K@c_old) and per-class partials of K^T@r_new
        for (int c = 0; c < NC; c++) {
            float c0 = cv[2 * c], c1 = cv[2 * c + 1];
            float s0 = 0.f, s1 = 0.f;
            #pragma unroll
            for (int st = 0; st < 2; st++) {
                int i2 = t + (2 * c + st) * 1024;   // class(i2*2) == c for all t
                int i = 2 * i2;
                float4 kk = Km4[i2];
                float rn0 = u / (kk.x * c0 + kk.y * c1);
                float rn1 = u / (kk.z * c0 + kk.w * c1);
                errp += fabsf(rn0 - rg[i]) + fabsf(rn1 - rg[i + 1]);
                rg[i] = rn0; rg[i + 1] = rn1;
                s0 += kk.x * rn0 + kk.z * rn1;
                s1 += kk.y * rn0 + kk.w * rn1;
            }
            #pragma unroll
            for (int o = 16; o; o >>= 1) {
                s0 += __shfl_xor_sync(0xffffffffu, s0, o);
                s1 += __shfl_xor_sync(0xffffffffu, s1, o);
            }
            if (!lane) { spart[c][wid][0] = s0; spart[c][wid][1] = s1; }
        }
        red[t] = errp;
        __syncthreads();
        for (int s = 512; s; s >>= 1) { if (t < s) red[t] += red[t + s]; __syncthreads(); }
        // all pass work done; safe to overwrite cv (deterministic 32-way sum)
        if (t < NJ) {
            int c = t >> 1, k = t & 1;
            float s = 0.f;
            #pragma unroll
            for (int w = 0; w < 32; w++) s += spart[c][w][k];
            cv[t] = v / s;
        }
        if (!t) errS = red[0] / (float)(NC * HW);
        __syncthreads();
        if (errS < 0.01f) break;
    }
    if (t < NJ) g_cv[n * NJ + t] = cv[t];
}

// ---------------- 8. T output: full-chip elementwise r*c*K, block per (n,c) ----------------
__global__ void __launch_bounds__(512) k_tout(float* __restrict__ Tout) {
    int bc = blockIdx.x, n = bc / NC, c = bc % NC, t = threadIdx.x;
    const float2* Km2 = (const float2*)g_Kmat + (size_t)bc * HW;
    const float* rp = g_r + (size_t)bc * HW;
    float cv0 = g_cv[n * NJ + 2 * c], cv1 = g_cv[n * NJ + 2 * c + 1];
    float* T0 = Tout + (size_t)bc * 2 * HW;   // [n][c][k=0][m]
    float* T1 = T0 + HW;                      // [n][c][k=1][m]
    for (int m = t; m < HW; m += 512) {
        float2 kk = Km2[m];
        float r = rp[m];
        T0[m] = r * cv0 * kk.x;
        T1[m] = r * cv1 * kk.y;
    }
}

// ---------------- launcher (single stream; fork reverted) ----------------
extern "C" void kernel_launch(void* const* d_in, const int* in_sizes, int n_in,
                              void* d_out, int out_size) {
    const float* norm_cam = (const float*)d_in[0];   // [8,21,64,64]
    const float* label    = (const float*)d_in[1];   // [8,21,1,1]
    const float* feature  = (const float*)d_in[2];   // [8,768,64,64]
    float* out  = (float*)d_out;                     // [8,21,64,64]
    float* Tout = out + NB * NC * HW;                // [8,21,2,64,64]

    const int KMEANS_SMEM = (2 * CF + KW * 2 * CF) * sizeof(float);      // 55296 B
    const int GEMM_SMEM   = GT * 256 * 4 + NJ * GT * 8;                  // 65280 B
    cudaFuncSetAttribute(k_kmeans, cudaFuncAttributeMaxDynamicSharedMemorySize, KMEANS_SMEM);
    cudaFuncSetAttribute(k_gemm,   cudaFuncAttributeMaxDynamicSharedMemorySize, GEMM_SMEM);

    k_transpose<<<dim3(HW / 128, CF / 32, NB), 256>>>(feature);
    k_fnfin   <<<(NB * HW + 255) / 256, 256>>>();
    k_argmax  <<<(NB * HW + 255) / 256, 256>>>(norm_cam, label);
    k_lists   <<<NB, 672>>>();
    k_kmeans  <<<NB * NC, 32 * KW, KMEANS_SMEM>>>();
    k_gemm    <<<dim3(HW / 256, NB), 256, GEMM_SMEM>>>(feature);
    k_camkmat <<<NB * NC, 512>>>(label, out);
    k_sinkhorn<<<NB, 1024>>>();
    k_tout    <<<NB * NC, 512>>>(Tout);
}

// round 11
// speedup vs baseline: 1.2672x; 1.1021x over previous
#include <cuda_runtime.h>
#include <math.h>

#define NB 8
#define NC 21
#define HW 4096
#define CF 768
#define NJ 42   // NC * 2
#define SKB 3   // sinkhorn blocks per image
#define SKC 7   // classes per sinkhorn block

// ---------------- scratch (__device__ globals; no allocation allowed) ----------------
__device__ float g_featT[NB * HW * CF];   // [n][m][d]
__device__ float g_fpart[24 * NB * HW];   // per-d-tile partial sumsq
__device__ float g_fnorm[NB * HW];        // ||feat[n,m]||
__device__ int   g_pcls[NB * HW];         // class of pixel if valid else -1
__device__ int   g_list[NB * NC * HW];    // valid pixel indices per (n,c), ascending
__device__ int   g_cnt[NB * NC];
__device__ float g_cent[NB * NJ * CF];    // [n][c*2+k][d]
__device__ float g_cnorm[NB * NJ];
__device__ float g_D[NB * NJ * HW];       // [n][j][m] = centers[j] . feat[m]
__device__ float g_Kmat[NB * NC * HW * 2];// [n][c][m][k]
__device__ float g_r[NB * NC * HW];
__device__ float g_cv[NB * NJ];           // sinkhorn column scalings
__device__ int   g_job;                   // kmeans work queue (reset by k_lists)
__device__ int   g_bar[NB][2];            // sinkhorn phase barriers (reset by k_camkmat)
__device__ float g_errp[NB][2][SKB];      // sinkhorn err partials, double-buffered

// packed f32x2 FMA (FFMA2): d = a*b + d, lane-wise on 2 packed floats
#define FMA_F32X2(d, a, b) \
    asm("fma.rn.f32x2 %0, %1, %2, %0;" : "+l"(d) : "l"(a), "l"(b))

// ---- 1. transpose feature (float4 both sides) + per-column partial sumsq ----
__global__ void __launch_bounds__(256) k_transpose(const float* __restrict__ feat) {
    __shared__ float tile[32][129];
    int n = blockIdx.z;
    int d0 = blockIdx.y * 32, m0 = blockIdx.x * 128;
    int t = threadIdx.x;
    #pragma unroll
    for (int i = 0; i < 4; i++) {
        int li = t + i * 256;
        int r = li >> 5, c4 = li & 31;
        float4 v = *(const float4*)&feat[((size_t)(n * CF + d0 + r)) * HW + m0 + c4 * 4];
        tile[r][c4 * 4 + 0] = v.x;
        tile[r][c4 * 4 + 1] = v.y;
        tile[r][c4 * 4 + 2] = v.z;
        tile[r][c4 * 4 + 3] = v.w;
    }
    __syncthreads();
    #pragma unroll
    for (int i = 0; i < 4; i++) {
        int li = t + i * 256;
        int m = li >> 3, d4 = li & 7;
        float4 v;
        v.x = tile[d4 * 4 + 0][m];
        v.y = tile[d4 * 4 + 1][m];
        v.z = tile[d4 * 4 + 2][m];
        v.w = tile[d4 * 4 + 3][m];
        *(float4*)&g_featT[((size_t)(n * HW + m0 + m)) * CF + d0 + d4 * 4] = v;
        float ss = v.x * v.x + v.y * v.y + v.z * v.z + v.w * v.w;
        #pragma unroll
        for (int o = 1; o < 8; o <<= 1) ss += __shfl_xor_sync(0xffffffffu, ss, o);
        if (d4 == 0) g_fpart[blockIdx.y * (NB * HW) + n * HW + m0 + m] = ss;
    }
}

// ---------------- 2. finalize feature norms (deterministic 24-way sum) ----------------
__global__ void k_fnfin() {
    int idx = blockIdx.x * blockDim.x + threadIdx.x;
    if (idx >= NB * HW) return;
    float s = 0.f;
    #pragma unroll
    for (int k = 0; k < 24; k++) s += g_fpart[k * (NB * HW) + idx];
    g_fnorm[idx] = sqrtf(s);
}

// ---------------- 3a. per-pixel argmax class, full-chip elementwise ----------------
__global__ void k_argmax(const float* __restrict__ cam, const float* __restrict__ label) {
    int idx = blockIdx.x * blockDim.x + threadIdx.x;
    if (idx >= NB * HW) return;
    int n = idx >> 12, m = idx & (HW - 1);
    const float* cp = cam + (size_t)n * NC * HW + m;
    float best = cp[0];
    int bi = 0;
    #pragma unroll
    for (int c = 1; c < NC; c++) {
        float v = cp[c * HW];
        if (v > best) { best = v; bi = c; }   // first max on ties
    }
    g_pcls[idx] = (label[n * NC + bi] > 0.f) ? bi : -1;
}

// ---- 3b. ordered compaction, block per (n,c): thread owns 32-px segment, block scan ----
__global__ void __launch_bounds__(128) k_lists() {
    __shared__ int wt[4];
    int bc = blockIdx.x, n = bc / NC, c = bc % NC, t = threadIdx.x;
    int wid = t >> 5, lane = t & 31;
    if (bc == 0 && t == 0) g_job = 0;    // reset kmeans work queue for this replay
    // load my 32-pixel segment (one 128B line per thread, int4 x8)
    int4 v[8];
    const int4* pp = (const int4*)(g_pcls + (size_t)n * HW) + t * 8;
    int cnt = 0;
    #pragma unroll
    for (int i = 0; i < 8; i++) {
        v[i] = pp[i];
        cnt += (v[i].x == c) + (v[i].y == c) + (v[i].z == c) + (v[i].w == c);
    }
    // warp inclusive scan
    int incl = cnt;
    #pragma unroll
    for (int o = 1; o < 32; o <<= 1) {
        int pv = __shfl_up_sync(0xffffffffu, incl, o);
        if (lane >= o) incl += pv;
    }
    if (lane == 31) wt[wid] = incl;
    __syncthreads();
    int woff = 0;
    #pragma unroll
    for (int w = 0; w < 4; w++) woff += (w < wid) ? wt[w] : 0;
    int off = woff + incl - cnt;         // exclusive prefix = my write offset
    // ordered writes: segment-major x element order == ascending pixel index
    int* lst = g_list + (size_t)bc * HW;
    int base = t * 32;
    #pragma unroll
    for (int i = 0; i < 8; i++) {
        if (v[i].x == c) lst[off++] = base + i * 4 + 0;
        if (v[i].y == c) lst[off++] = base + i * 4 + 1;
        if (v[i].z == c) lst[off++] = base + i * 4 + 2;
        if (v[i].w == c) lst[off++] = base + i * 4 + 3;
    }
    if (t == 0) g_cnt[bc] = wt[0] + wt[1] + wt[2] + wt[3];
}

// ---- 4. k-means: persistent blocks + work queue; 8 warps, 2-px ILP, pipelined, early-exit ----
#define KW 8   // warps per kmeans block

#define LOADPAIR(VA, VB, HAS, PI) {                                   \
    int _m0 = lst[PI];                                                \
    HAS = (PI + 1 < cnt);                                             \
    int _m1 = HAS ? lst[(PI) + 1] : _m0;                              \
    const float4* _fa = (const float4*)(fbase + (size_t)_m0 * CF) + lane; \
    const float4* _fb = (const float4*)(fbase + (size_t)_m1 * CF) + lane; \
    _Pragma("unroll")                                                 \
    for (int _j = 0; _j < 6; _j++) {                                  \
        VA[_j] = _fa[_j * 32];                                        \
        VB[_j] = _fb[_j * 32];                                        \
    } }

#define DOTPAIR(VA, VB) {                                             \
    d0a = 0.f; d1a = 0.f; d0b = 0.f; d1b = 0.f;                       \
    _Pragma("unroll")                                                 \
    for (int _j = 0; _j < 6; _j++) {                                  \
        float4 _c0 = cen4[lane + _j * 32];                            \
        float4 _c1 = cen4[48 * 4 + lane + _j * 32];                   \
        d0a += VA[_j].x * _c0.x + VA[_j].y * _c0.y                    \
             + VA[_j].z * _c0.z + VA[_j].w * _c0.w;                   \
        d1a += VA[_j].x * _c1.x + VA[_j].y * _c1.y                    \
             + VA[_j].z * _c1.z + VA[_j].w * _c1.w;                   \
        d0b += VB[_j].x * _c0.x + VB[_j].y * _c0.y                    \
             + VB[_j].z * _c0.z + VB[_j].w * _c0.w;                   \
        d1b += VB[_j].x * _c1.x + VB[_j].y * _c1.y                    \
             + VB[_j].z * _c1.z + VB[_j].w * _c1.w;                   \
    } }

#define FINPAIR(VA, VB, HAS, PI) {                                    \
    _Pragma("unroll")                                                 \
    for (int _o = 16; _o; _o >>= 1) {                                 \
        d0a += __shfl_xor_sync(0xffffffffu, d0a, _o);                 \
        d1a += __shfl_xor_sync(0xffffffffu, d1a, _o);                 \
        d0b += __shfl_xor_sync(0xffffffffu, d0b, _o);                 \
        d1b += __shfl_xor_sync(0xffffffffu, d1b, _o);                 \
    }                                                                 \
    int _aa = (d1a * inv1 > d0a * inv0) ? 1 : 0;                      \
    int _ab = (d1b * inv1 > d0b * inv0) ? 1 : 0;                      \
    if (!lane) {                                                      \
        if (iter > 0) mychg += (sprev[PI] != _aa)                     \
                             + (HAS ? (sprev[(PI) + 1] != _ab) : 0);  \
        sprev[PI] = (unsigned char)_aa;                               \
        if (HAS) sprev[(PI) + 1] = (unsigned char)_ab;                \
    }                                                                 \
    float _w0a = _aa ? 0.f : 1.f, _w1a = _aa ? 1.f : 0.f;             \
    float _w0b = 0.f, _w1b = 0.f;                                     \
    if (HAS) { _w0b = _ab ? 0.f : 1.f; _w1b = _ab ? 1.f : 0.f; }      \
    _Pragma("unroll")                                                 \
    for (int _j = 0; _j < 6; _j++) {                                  \
        acc0[_j].x = fmaf(_w0a, VA[_j].x, fmaf(_w0b, VB[_j].x, acc0[_j].x)); \
        acc0[_j].y = fmaf(_w0a, VA[_j].y, fmaf(_w0b, VB[_j].y, acc0[_j].y)); \
        acc0[_j].z = fmaf(_w0a, VA[_j].z, fmaf(_w0b, VB[_j].z, acc0[_j].z)); \
        acc0[_j].w = fmaf(_w0a, VA[_j].w, fmaf(_w0b, VB[_j].w, acc0[_j].w)); \
        acc1[_j].x = fmaf(_w1a, VA[_j].x, fmaf(_w1b, VB[_j].x, acc1[_j].x)); \
        acc1[_j].y = fmaf(_w1a, VA[_j].y, fmaf(_w1b, VB[_j].y, acc1[_j].y)); \
        acc1[_j].z = fmaf(_w1a, VA[_j].z, fmaf(_w1b, VB[_j].z, acc1[_j].z)); \
        acc1[_j].w = fmaf(_w1a, VA[_j].w, fmaf(_w1b, VB[_j].w, acc1[_j].w)); \
    }                                                                 \
    myc0 += (1 - _aa) + (HAS ? (1 - _ab) : 0);                        \
    myc1 += _aa + (HAS ? _ab : 0); }

__global__ void __launch_bounds__(32 * KW) k_kmeans() {
    extern __shared__ float buf[];
    float* cen  = buf;            // [2][CF]
    float* part = buf + 2 * CF;   // [KW][2][CF]
    float4* cen4 = (float4*)cen;
    __shared__ unsigned char sprev[HW];
    __shared__ int   pcnt[KW][2];
    __shared__ int   pchg[KW];
    __shared__ float inv_s[2];
    __shared__ int   cnts[2], schg, jobS;
    int t = threadIdx.x, wid = t >> 5, lane = t & 31;

    for (;;) {
        if (t == 0) jobS = atomicAdd(&g_job, 1);
        __syncthreads();
        int bc = jobS;
        __syncthreads();
        if (bc >= NB * NC) return;
        int n = bc / NC;
        int cnt = g_cnt[bc];
        float* gc = g_cent + (size_t)bc * 2 * CF;
        if (cnt < 2) {   // reference: centers forced to zero
            for (int i = t; i < 2 * CF; i += 32 * KW) gc[i] = 0.f;
            if (t < 2) g_cnorm[bc * 2 + t] = 0.f;
            __syncthreads();
            continue;
        }
        const int* lst = g_list + (size_t)bc * HW;
        const float* fbase = g_featT + (size_t)n * HW * CF;
        int i0 = lst[0], i1 = lst[1];
        for (int d = t; d < CF; d += 32 * KW) {
            cen[d]      = fbase[(size_t)i0 * CF + d];
            cen[CF + d] = fbase[(size_t)i1 * CF + d];
        }
        __syncthreads();

        for (int iter = 0; iter < 10; iter++) {
            if (wid < 2) {   // center inverse norms
                float s = 0.f;
                for (int d = lane; d < CF; d += 32) { float v = cen[wid * CF + d]; s += v * v; }
                #pragma unroll
                for (int o = 16; o; o >>= 1) s += __shfl_xor_sync(0xffffffffu, s, o);
                if (!lane) inv_s[wid] = 1.f / fmaxf(sqrtf(s), 1e-8f);
            }
            __syncthreads();
            float inv0 = inv_s[0], inv1 = inv_s[1];
            float4 acc0[6], acc1[6];
            #pragma unroll
            for (int j = 0; j < 6; j++) {
                acc0[j] = make_float4(0.f, 0.f, 0.f, 0.f);
                acc1[j] = make_float4(0.f, 0.f, 0.f, 0.f);
            }
            int myc0 = 0, myc1 = 0, mychg = 0;

            float4 vax[6], vbx[6], vay[6], vby[6];
            float d0a, d1a, d0b, d1b;
            int hasx = 0, hasy = 0;
            int pi = wid * 2;
            if (pi < cnt) LOADPAIR(vax, vbx, hasx, pi);
            while (pi < cnt) {
                int pj = pi + 2 * KW;
                if (pj < cnt) LOADPAIR(vay, vby, hasy, pj);
                DOTPAIR(vax, vbx);
                FINPAIR(vax, vbx, hasx, pi);
                pi = pj;
                if (pi >= cnt) break;
                pj = pi + 2 * KW;
                if (pj < cnt) LOADPAIR(vax, vbx, hasx, pj);
                DOTPAIR(vay, vby);
                FINPAIR(vay, vby, hasy, pi);
                pi = pj;
            }

            float4* p0 = (float4*)&part[(wid * 2 + 0) * CF];
            float4* p1 = (float4*)&part[(wid * 2 + 1) * CF];
            #pragma unroll
            for (int j = 0; j < 6; j++) {
                p0[lane + j * 32] = acc0[j];
                p1[lane + j * 32] = acc1[j];
            }
            if (!lane) { pcnt[wid][0] = myc0; pcnt[wid][1] = myc1; pchg[wid] = mychg; }
            __syncthreads();
            if (t < 2) {
                int s = 0;
                #pragma unroll
                for (int w2 = 0; w2 < KW; w2++) s += pcnt[w2][t];
                cnts[t] = s;
            }
            if (t == 2) {
                int s = 0;
                #pragma unroll
                for (int w2 = 0; w2 < KW; w2++) s += pchg[w2];
                schg = s;
            }
            __syncthreads();
            float div0 = 1.f / fmaxf((float)cnts[0], 1.f);
            float div1 = 1.f / fmaxf((float)cnts[1], 1.f);
            for (int d = t; d < CF; d += 32 * KW) {
                float s0 = 0.f, s1 = 0.f;
                #pragma unroll
                for (int w2 = 0; w2 < KW; w2++) {
                    s0 += part[(w2 * 2) * CF + d];
                    s1 += part[(w2 * 2 + 1) * CF + d];
                }
                cen[d] = s0 * div0;
                cen[CF + d] = s1 * div1;
            }
            __syncthreads();
            if (iter > 0 && schg == 0) break;   // fixed point
        }
        for (int d = t; d < CF; d += 32 * KW) { gc[d] = cen[d]; gc[CF + d] = cen[CF + d]; }
        if (wid < 2) {
            float s = 0.f;
            for (int d = lane; d < CF; d += 32) { float v = cen[wid * CF + d]; s += v * v; }
            #pragma unroll
            for (int o = 16; o; o >>= 1) s += __shfl_xor_sync(0xffffffffu, s, o);
            if (!lane) g_cnorm[bc * 2 + wid] = sqrtf(s);
        }
        __syncthreads();   // protect smem before next job
    }
}

// ---- 5. GEMM via packed f32x2 FMA, 256 threads: D[n][j][m] = centers[n][j].feat[n][m] ----
#define GT 48   // k-tile
__global__ void __launch_bounds__(256) k_gemm(const float* __restrict__ feat) {
    extern __shared__ float sm[];
    float* fS = sm;                                            // [GT][256]
    unsigned long long* cS2 = (unsigned long long*)(sm + GT * 256);  // [NJ][GT]
    int n = blockIdx.y, m0 = blockIdx.x * 256;
    int t = threadIdx.x;
    int p = t & 127, g = t >> 7;
    unsigned long long acc[21];
    #pragma unroll
    for (int j = 0; j < 21; j++) acc[j] = 0ull;

    for (int k0 = 0; k0 < CF; k0 += GT) {
        __syncthreads();
        for (int idx = t; idx < GT * 64; idx += 256) {
            int dd = idx >> 6, c4 = idx & 63;
            float4 v = *(const float4*)&feat[((size_t)(n * CF + k0 + dd)) * HW + m0 + c4 * 4];
            *(float4*)&fS[dd * 256 + c4 * 4] = v;
        }
        for (int idx = t; idx < NJ * GT; idx += 256) {
            int j = idx / GT, dd = idx % GT;
            float v = g_cent[((size_t)n * NJ + j) * CF + k0 + dd];
            float2 d2 = make_float2(v, v);
            cS2[j * GT + dd] = *(unsigned long long*)&d2;
        }
        __syncthreads();
        #pragma unroll 4
        for (int dd = 0; dd < GT; dd += 2) {
            unsigned long long a0 = *(const unsigned long long*)&fS[dd * 256 + 2 * p];
            unsigned long long a1 = *(const unsigned long long*)&fS[(dd + 1) * 256 + 2 * p];
            #pragma unroll
            for (int j = 0; j < 21; j++) {
                ulonglong2 c2 = *(const ulonglong2*)&cS2[(g * 21 + j) * GT + dd];
                FMA_F32X2(acc[j], a0, c2.x);
                FMA_F32X2(acc[j], a1, c2.y);
            }
        }
    }
    #pragma unroll
    for (int j = 0; j < 21; j++) {
        float* dp = g_D + ((size_t)n * NJ + g * 21 + j) * HW + m0;
        *(float2*)&dp[2 * p] = *(float2*)&acc[j];
    }
}

// ---------------- 6. fused cam + per-map max-normalize + Sinkhorn K matrix ----------------
__global__ void __launch_bounds__(512) k_camkmat(const float* __restrict__ label,
                                                 float* __restrict__ out) {
    __shared__ float scam[HW];
    __shared__ float red[512];
    int bc = blockIdx.x, n = bc / NC, c = bc % NC, t = threadIdx.x;
    if (bc == 0 && t < NB * 2) ((int*)g_bar)[t] = 0;   // reset sinkhorn barriers each replay
    int cnt = g_cnt[bc];
    float lab = label[bc];
    float inv_cn0 = 1.f / fmaxf(g_cnorm[n * NJ + 2 * c], 1e-8f);
    float inv_cn1 = 1.f / fmaxf(g_cnorm[n * NJ + 2 * c + 1], 1e-8f);
    float ik0 = 1.f / (g_cnorm[n * NJ + c] + 1e-5f);         // kmat quirk: j = k*21 + c
    float ik1 = 1.f / (g_cnorm[n * NJ + NC + c] + 1e-5f);
    const float* D0  = g_D + ((size_t)n * NJ + 2 * c) * HW;
    const float* D1  = D0 + HW;
    const float* Dk0 = g_D + ((size_t)n * NJ + c) * HW;
    const float* Dk1 = g_D + ((size_t)n * NJ + NC + c) * HW;
    float2* Km2 = (float2*)(g_Kmat + (size_t)bc * HW * 2);
    float mx = -INFINITY;
    for (int m = t; m < HW; m += 512) {
        float fn = g_fnorm[n * HW + m];
        float camv = 0.f;
        if (cnt >= 2) {
            float fi = 1.f / fmaxf(fn, 1e-8f);
            camv = 0.5f * (D0[m] * inv_cn0 + D1[m] * inv_cn1) * fi * lab;
        }
        scam[m] = camv;
        mx = fmaxf(mx, camv);
        float fk = 1.f / (fn + 1e-5f);
        float2 kk;
        kk.x = __expf((Dk0[m] * fk * ik0 - 1.f) * 10.f);
        kk.y = __expf((Dk1[m] * fk * ik1 - 1.f) * 10.f);
        Km2[m] = kk;
    }
    red[t] = mx;
    __syncthreads();
    for (int s = 256; s; s >>= 1) { if (t < s) red[t] = fmaxf(red[t], red[t + s]); __syncthreads(); }
    float inv = 1.f / (red[0] + 1e-5f);
    for (int m = t; m < HW; m += 512) out[(size_t)bc * HW + m] = scam[m] * inv;
}

// ---- 7. Sinkhorn: 3 blocks per n (7 classes each), software barrier for the global
//        early-stop (err = mean over ALL classes, faithful to reference) ----
__global__ void __launch_bounds__(1024) k_sinkhorn() {
    __shared__ float cv[2 * SKC];
    __shared__ float spart[SKC][32][2];
    __shared__ float red[1024];
    __shared__ float errS;
    int blk = blockIdx.x;
    int n = blk / SKB, b = blk % SKB;
    int c0 = b * SKC;
    int t = threadIdx.x, lane = t & 31, wid = t >> 5;
    const float u = 1.f / (float)HW, v = 0.5f;
    float* rg = g_r + (size_t)n * NC * HW;
    const float4* Km4 = (const float4*)(g_Kmat + (size_t)n * NC * HW * 2);
    if (t < 2 * SKC) cv[t] = 1.f;
    for (int i = t; i < SKC * HW; i += 1024) rg[c0 * HW + i] = 1.f;
    __syncthreads();

    for (int it = 0; it < 100; it++) {
        float errp = 0.f;
        for (int cc = 0; cc < SKC; cc++) {
            int c = c0 + cc;
            float cv0 = cv[2 * cc], cv1 = cv[2 * cc + 1];
            float s0 = 0.f, s1 = 0.f;
            #pragma unroll
            for (int st = 0; st < 2; st++) {
                int i2 = t + (2 * c + st) * 1024;
                int i = 2 * i2;
                float4 kk = Km4[i2];
                float rn0 = u / (kk.x * cv0 + kk.y * cv1);
                float rn1 = u / (kk.z * cv0 + kk.w * cv1);
                errp += fabsf(rn0 - rg[i]) + fabsf(rn1 - rg[i + 1]);
                rg[i] = rn0; rg[i + 1] = rn1;
                s0 += kk.x * rn0 + kk.z * rn1;
                s1 += kk.y * rn0 + kk.w * rn1;
            }
            #pragma unroll
            for (int o = 16; o; o >>= 1) {
                s0 += __shfl_xor_sync(0xffffffffu, s0, o);
                s1 += __shfl_xor_sync(0xffffffffu, s1, o);
            }
            if (!lane) { spart[cc][wid][0] = s0; spart[cc][wid][1] = s1; }
        }
        red[t] = errp;
        __syncthreads();
        for (int s = 512; s; s >>= 1) { if (t < s) red[t] += red[t + s]; __syncthreads(); }
        // local c-update (independent of other blocks)
        if (t < 2 * SKC) {
            int cc = t >> 1, k = t & 1;
            float s = 0.f;
            #pragma unroll
            for (int w = 0; w < 32; w++) s += spart[cc][w][k];
            cv[t] = v / s;
        }
        // publish err partial (double-buffered by phase), arrive, spin to target
        int ph = it & 1;
        if (t == 0) {
            g_errp[n][ph][b] = red[0];
            __threadfence();
            atomicAdd(&g_bar[n][ph], 1);
            int target = SKB * ((it >> 1) + 1);   // monotonic, no resets needed
            while (atomicAdd(&g_bar[n][ph], 0) < target) { }
            __threadfence();
            // deterministic fixed-order 3-way sum
            errS = (g_errp[n][ph][0] + g_errp[n][ph][1] + g_errp[n][ph][2])
                   / (float)(NC * HW);
        }
        __syncthreads();
        if (errS < 0.01f) break;   // identical decision in all SKB blocks
    }
    if (t < 2 * SKC) g_cv[n * NJ + 2 * c0 + t] = cv[t];
}

// ---------------- 8. T output: full-chip elementwise r*c*K, block per (n,c) ----------------
__global__ void __launch_bounds__(512) k_tout(float* __restrict__ Tout) {
    int bc = blockIdx.x, n = bc / NC, c = bc % NC, t = threadIdx.x;
    const float2* Km2 = (const float2*)g_Kmat + (size_t)bc * HW;
    const float* rp = g_r + (size_t)bc * HW;
    float cv0 = g_cv[n * NJ + 2 * c], cv1 = g_cv[n * NJ + 2 * c + 1];
    float* T0 = Tout + (size_t)bc * 2 * HW;
    float* T1 = T0 + HW;
    for (int m = t; m < HW; m += 512) {
        float2 kk = Km2[m];
        float r = rp[m];
        T0[m] = r * cv0 * kk.x;
        T1[m] = r * cv1 * kk.y;
    }
}

// ---------------- launcher ----------------
extern "C" void kernel_launch(void* const* d_in, const int* in_sizes, int n_in,
                              void* d_out, int out_size) {
    const float* norm_cam = (const float*)d_in[0];   // [8,21,64,64]
    const float* label    = (const float*)d_in[1];   // [8,21,1,1]
    const float* feature  = (const float*)d_in[2];   // [8,768,64,64]
    float* out  = (float*)d_out;                     // [8,21,64,64]
    float* Tout = out + NB * NC * HW;                // [8,21,2,64,64]

    const int KMEANS_SMEM = (2 * CF + KW * 2 * CF) * sizeof(float);      // 55296 B
    const int GEMM_SMEM   = GT * 256 * 4 + NJ * GT * 8;                  // 65280 B
    cudaFuncSetAttribute(k_kmeans, cudaFuncAttributeMaxDynamicSharedMemorySize, KMEANS_SMEM);
    cudaFuncSetAttribute(k_gemm,   cudaFuncAttributeMaxDynamicSharedMemorySize, GEMM_SMEM);

    k_transpose<<<dim3(HW / 128, CF / 32, NB), 256>>>(feature);
    k_fnfin   <<<(NB * HW + 255) / 256, 256>>>();
    k_argmax  <<<(NB * HW + 255) / 256, 256>>>(norm_cam, label);
    k_lists   <<<NB * NC, 128>>>();
    k_kmeans  <<<148, 32 * KW, KMEANS_SMEM>>>();
    k_gemm    <<<dim3(HW / 256, NB), 256, GEMM_SMEM>>>(feature);
    k_camkmat <<<NB * NC, 512>>>(label, out);
    k_sinkhorn<<<NB * SKB, 1024>>>();
    k_tout    <<<NB * NC, 512>>>(Tout);
}

// round 12
// speedup vs baseline: 1.2789x; 1.0092x over previous
#include <cuda_runtime.h>
#include <math.h>

#define NB 8
#define NC 21
#define HW 4096
#define CF 768
#define NJ 42   // NC * 2
#define SKB 3   // sinkhorn blocks per image
#define SKC 7   // classes per sinkhorn block

// ---------------- scratch (__device__ globals; no allocation allowed) ----------------
__device__ float g_featT[NB * HW * CF];   // [n][m][d]
__device__ float g_fpart[24 * NB * HW];   // per-d-tile partial sumsq
__device__ float g_fnorm[NB * HW];        // ||feat[n,m]||
__device__ int   g_pcls[NB * HW];         // class of pixel if valid else -1
__device__ int   g_list[NB * NC * HW];    // valid pixel indices per (n,c), ascending
__device__ int   g_cnt[NB * NC];
__device__ float g_cent[NB * NJ * CF];    // [n][c*2+k][d]
__device__ float g_cnorm[NB * NJ];
__device__ float g_D[NB * NJ * HW];       // [n][j][m] = centers[j] . feat[m]
__device__ float g_Kmat[NB * NC * HW * 2];// [n][c][m][k]
__device__ float g_r[NB * NC * HW];
__device__ float g_cv[NB * NJ];           // sinkhorn column scalings
__device__ int   g_job;                   // kmeans work queue (reset by k_lists)
__device__ int   g_bar[NB][2];            // sinkhorn phase barriers (reset by k_camkmat)
__device__ float g_errp[NB][2][SKB];      // sinkhorn err partials, double-buffered

// packed f32x2 FMA (FFMA2): d = a*b + d, lane-wise on 2 packed floats
#define FMA_F32X2(d, a, b) \
    asm("fma.rn.f32x2 %0, %1, %2, %0;" : "+l"(d) : "l"(a), "l"(b))

// ---- 1. transpose feature (float4 both sides) + per-column partial sumsq ----
__global__ void __launch_bounds__(256) k_transpose(const float* __restrict__ feat) {
    __shared__ float tile[32][129];
    int n = blockIdx.z;
    int d0 = blockIdx.y * 32, m0 = blockIdx.x * 128;
    int t = threadIdx.x;
    #pragma unroll
    for (int i = 0; i < 4; i++) {
        int li = t + i * 256;
        int r = li >> 5, c4 = li & 31;
        float4 v = *(const float4*)&feat[((size_t)(n * CF + d0 + r)) * HW + m0 + c4 * 4];
        tile[r][c4 * 4 + 0] = v.x;
        tile[r][c4 * 4 + 1] = v.y;
        tile[r][c4 * 4 + 2] = v.z;
        tile[r][c4 * 4 + 3] = v.w;
    }
    __syncthreads();
    #pragma unroll
    for (int i = 0; i < 4; i++) {
        int li = t + i * 256;
        int m = li >> 3, d4 = li & 7;
        float4 v;
        v.x = tile[d4 * 4 + 0][m];
        v.y = tile[d4 * 4 + 1][m];
        v.z = tile[d4 * 4 + 2][m];
        v.w = tile[d4 * 4 + 3][m];
        *(float4*)&g_featT[((size_t)(n * HW + m0 + m)) * CF + d0 + d4 * 4] = v;
        float ss = v.x * v.x + v.y * v.y + v.z * v.z + v.w * v.w;
        #pragma unroll
        for (int o = 1; o < 8; o <<= 1) ss += __shfl_xor_sync(0xffffffffu, ss, o);
        if (d4 == 0) g_fpart[blockIdx.y * (NB * HW) + n * HW + m0 + m] = ss;
    }
}

// ---------------- 2. finalize feature norms (deterministic 24-way sum) ----------------
__global__ void k_fnfin() {
    int idx = blockIdx.x * blockDim.x + threadIdx.x;
    if (idx >= NB * HW) return;
    float s = 0.f;
    #pragma unroll
    for (int k = 0; k < 24; k++) s += g_fpart[k * (NB * HW) + idx];
    g_fnorm[idx] = sqrtf(s);
}

// ---------------- 3a. per-pixel argmax class, full-chip elementwise ----------------
__global__ void k_argmax(const float* __restrict__ cam, const float* __restrict__ label) {
    int idx = blockIdx.x * blockDim.x + threadIdx.x;
    if (idx >= NB * HW) return;
    int n = idx >> 12, m = idx & (HW - 1);
    const float* cp = cam + (size_t)n * NC * HW + m;
    float best = cp[0];
    int bi = 0;
    #pragma unroll
    for (int c = 1; c < NC; c++) {
        float v = cp[c * HW];
        if (v > best) { best = v; bi = c; }   // first max on ties
    }
    g_pcls[idx] = (label[n * NC + bi] > 0.f) ? bi : -1;
}

// ---- 3b. ordered compaction, block per (n,c): thread owns 32-px segment, block scan ----
__global__ void __launch_bounds__(128) k_lists() {
    __shared__ int wt[4];
    int bc = blockIdx.x, n = bc / NC, c = bc % NC, t = threadIdx.x;
    int wid = t >> 5, lane = t & 31;
    if (bc == 0 && t == 0) g_job = 0;    // reset kmeans work queue for this replay
    int4 v[8];
    const int4* pp = (const int4*)(g_pcls + (size_t)n * HW) + t * 8;
    int cnt = 0;
    #pragma unroll
    for (int i = 0; i < 8; i++) {
        v[i] = pp[i];
        cnt += (v[i].x == c) + (v[i].y == c) + (v[i].z == c) + (v[i].w == c);
    }
    int incl = cnt;
    #pragma unroll
    for (int o = 1; o < 32; o <<= 1) {
        int pv = __shfl_up_sync(0xffffffffu, incl, o);
        if (lane >= o) incl += pv;
    }
    if (lane == 31) wt[wid] = incl;
    __syncthreads();
    int woff = 0;
    #pragma unroll
    for (int w = 0; w < 4; w++) woff += (w < wid) ? wt[w] : 0;
    int off = woff + incl - cnt;         // exclusive prefix = my write offset
    int* lst = g_list + (size_t)bc * HW;
    int base = t * 32;
    #pragma unroll
    for (int i = 0; i < 8; i++) {
        if (v[i].x == c) lst[off++] = base + i * 4 + 0;
        if (v[i].y == c) lst[off++] = base + i * 4 + 1;
        if (v[i].z == c) lst[off++] = base + i * 4 + 2;
        if (v[i].w == c) lst[off++] = base + i * 4 + 3;
    }
    if (t == 0) g_cnt[bc] = wt[0] + wt[1] + wt[2] + wt[3];
}

// ---- 4. k-means: persistent blocks + work queue; 8 warps, 2-px ILP, pipelined, early-exit ----
#define KW 8   // warps per kmeans block

#define LOADPAIR(VA, VB, HAS, PI) {                                   \
    int _m0 = lst[PI];                                                \
    HAS = (PI + 1 < cnt);                                             \
    int _m1 = HAS ? lst[(PI) + 1] : _m0;                              \
    const float4* _fa = (const float4*)(fbase + (size_t)_m0 * CF) + lane; \
    const float4* _fb = (const float4*)(fbase + (size_t)_m1 * CF) + lane; \
    _Pragma("unroll")                                                 \
    for (int _j = 0; _j < 6; _j++) {                                  \
        VA[_j] = _fa[_j * 32];                                        \
        VB[_j] = _fb[_j * 32];                                        \
    } }

#define DOTPAIR(VA, VB) {                                             \
    d0a = 0.f; d1a = 0.f; d0b = 0.f; d1b = 0.f;                       \
    _Pragma("unroll")                                                 \
    for (int _j = 0; _j < 6; _j++) {                                  \
        float4 _c0 = cen4[lane + _j * 32];                            \
        float4 _c1 = cen4[48 * 4 + lane + _j * 32];                   \
        d0a += VA[_j].x * _c0.x + VA[_j].y * _c0.y                    \
             + VA[_j].z * _c0.z + VA[_j].w * _c0.w;                   \
        d1a += VA[_j].x * _c1.x + VA[_j].y * _c1.y                    \
             + VA[_j].z * _c1.z + VA[_j].w * _c1.w;                   \
        d0b += VB[_j].x * _c0.x + VB[_j].y * _c0.y                    \
             + VB[_j].z * _c0.z + VB[_j].w * _c0.w;                   \
        d1b += VB[_j].x * _c1.x + VB[_j].y * _c1.y                    \
             + VB[_j].z * _c1.z + VB[_j].w * _c1.w;                   \
    } }

#define FINPAIR(VA, VB, HAS, PI) {                                    \
    _Pragma("unroll")                                                 \
    for (int _o = 16; _o; _o >>= 1) {                                 \
        d0a += __shfl_xor_sync(0xffffffffu, d0a, _o);                 \
        d1a += __shfl_xor_sync(0xffffffffu, d1a, _o);                 \
        d0b += __shfl_xor_sync(0xffffffffu, d0b, _o);                 \
        d1b += __shfl_xor_sync(0xffffffffu, d1b, _o);                 \
    }                                                                 \
    int _aa = (d1a * inv1 > d0a * inv0) ? 1 : 0;                      \
    int _ab = (d1b * inv1 > d0b * inv0) ? 1 : 0;                      \
    if (!lane) {                                                      \
        if (iter > 0) mychg += (sprev[PI] != _aa)                     \
                             + (HAS ? (sprev[(PI) + 1] != _ab) : 0);  \
        sprev[PI] = (unsigned char)_aa;                               \
        if (HAS) sprev[(PI) + 1] = (unsigned char)_ab;                \
    }                                                                 \
    float _w0a = _aa ? 0.f : 1.f, _w1a = _aa ? 1.f : 0.f;             \
    float _w0b = 0.f, _w1b = 0.f;                                     \
    if (HAS) { _w0b = _ab ? 0.f : 1.f; _w1b = _ab ? 1.f : 0.f; }      \
    _Pragma("unroll")                                                 \
    for (int _j = 0; _j < 6; _j++) {                                  \
        acc0[_j].x = fmaf(_w0a, VA[_j].x, fmaf(_w0b, VB[_j].x, acc0[_j].x)); \
        acc0[_j].y = fmaf(_w0a, VA[_j].y, fmaf(_w0b, VB[_j].y, acc0[_j].y)); \
        acc0[_j].z = fmaf(_w0a, VA[_j].z, fmaf(_w0b, VB[_j].z, acc0[_j].z)); \
        acc0[_j].w = fmaf(_w0a, VA[_j].w, fmaf(_w0b, VB[_j].w, acc0[_j].w)); \
        acc1[_j].x = fmaf(_w1a, VA[_j].x, fmaf(_w1b, VB[_j].x, acc1[_j].x)); \
        acc1[_j].y = fmaf(_w1a, VA[_j].y, fmaf(_w1b, VB[_j].y, acc1[_j].y)); \
        acc1[_j].z = fmaf(_w1a, VA[_j].z, fmaf(_w1b, VB[_j].z, acc1[_j].z)); \
        acc1[_j].w = fmaf(_w1a, VA[_j].w, fmaf(_w1b, VB[_j].w, acc1[_j].w)); \
    }                                                                 \
    myc0 += (1 - _aa) + (HAS ? (1 - _ab) : 0);                        \
    myc1 += _aa + (HAS ? _ab : 0); }

__global__ void __launch_bounds__(32 * KW) k_kmeans() {
    extern __shared__ float buf[];
    float* cen  = buf;            // [2][CF]
    float* part = buf + 2 * CF;   // [KW][2][CF]
    float4* cen4 = (float4*)cen;
    __shared__ unsigned char sprev[HW];
    __shared__ int   pcnt[KW][2];
    __shared__ int   pchg[KW];
    __shared__ float inv_s[2];
    __shared__ int   cnts[2], schg, jobS;
    int t = threadIdx.x, wid = t >> 5, lane = t & 31;

    for (;;) {
        if (t == 0) jobS = atomicAdd(&g_job, 1);
        __syncthreads();
        int bc = jobS;
        __syncthreads();
        if (bc >= NB * NC) return;
        int n = bc / NC;
        int cnt = g_cnt[bc];
        float* gc = g_cent + (size_t)bc * 2 * CF;
        if (cnt < 2) {   // reference: centers forced to zero
            for (int i = t; i < 2 * CF; i += 32 * KW) gc[i] = 0.f;
            if (t < 2) g_cnorm[bc * 2 + t] = 0.f;
            __syncthreads();
            continue;
        }
        const int* lst = g_list + (size_t)bc * HW;
        const float* fbase = g_featT + (size_t)n * HW * CF;
        int i0 = lst[0], i1 = lst[1];
        for (int d = t; d < CF; d += 32 * KW) {
            cen[d]      = fbase[(size_t)i0 * CF + d];
            cen[CF + d] = fbase[(size_t)i1 * CF + d];
        }
        __syncthreads();

        for (int iter = 0; iter < 10; iter++) {
            if (wid < 2) {   // center inverse norms
                float s = 0.f;
                for (int d = lane; d < CF; d += 32) { float v = cen[wid * CF + d]; s += v * v; }
                #pragma unroll
                for (int o = 16; o; o >>= 1) s += __shfl_xor_sync(0xffffffffu, s, o);
                if (!lane) inv_s[wid] = 1.f / fmaxf(sqrtf(s), 1e-8f);
            }
            __syncthreads();
            float inv0 = inv_s[0], inv1 = inv_s[1];
            float4 acc0[6], acc1[6];
            #pragma unroll
            for (int j = 0; j < 6; j++) {
                acc0[j] = make_float4(0.f, 0.f, 0.f, 0.f);
                acc1[j] = make_float4(0.f, 0.f, 0.f, 0.f);
            }
            int myc0 = 0, myc1 = 0, mychg = 0;

            float4 vax[6], vbx[6], vay[6], vby[6];
            float d0a, d1a, d0b, d1b;
            int hasx = 0, hasy = 0;
            int pi = wid * 2;
            if (pi < cnt) LOADPAIR(vax, vbx, hasx, pi);
            while (pi < cnt) {
                int pj = pi + 2 * KW;
                if (pj < cnt) LOADPAIR(vay, vby, hasy, pj);
                DOTPAIR(vax, vbx);
                FINPAIR(vax, vbx, hasx, pi);
                pi = pj;
                if (pi >= cnt) break;
                pj = pi + 2 * KW;
                if (pj < cnt) LOADPAIR(vax, vbx, hasx, pj);
                DOTPAIR(vay, vby);
                FINPAIR(vay, vby, hasy, pi);
                pi = pj;
            }

            float4* p0 = (float4*)&part[(wid * 2 + 0) * CF];
            float4* p1 = (float4*)&part[(wid * 2 + 1) * CF];
            #pragma unroll
            for (int j = 0; j < 6; j++) {
                p0[lane + j * 32] = acc0[j];
                p1[lane + j * 32] = acc1[j];
            }
            if (!lane) { pcnt[wid][0] = myc0; pcnt[wid][1] = myc1; pchg[wid] = mychg; }
            __syncthreads();
            if (t < 2) {
                int s = 0;
                #pragma unroll
                for (int w2 = 0; w2 < KW; w2++) s += pcnt[w2][t];
                cnts[t] = s;
            }
            if (t == 2) {
                int s = 0;
                #pragma unroll
                for (int w2 = 0; w2 < KW; w2++) s += pchg[w2];
                schg = s;
            }
            __syncthreads();
            float div0 = 1.f / fmaxf((float)cnts[0], 1.f);
            float div1 = 1.f / fmaxf((float)cnts[1], 1.f);
            for (int d = t; d < CF; d += 32 * KW) {
                float s0 = 0.f, s1 = 0.f;
                #pragma unroll
                for (int w2 = 0; w2 < KW; w2++) {
                    s0 += part[(w2 * 2) * CF + d];
                    s1 += part[(w2 * 2 + 1) * CF + d];
                }
                cen[d] = s0 * div0;
                cen[CF + d] = s1 * div1;
            }
            __syncthreads();
            if (iter > 0 && schg == 0) break;   // fixed point
        }
        for (int d = t; d < CF; d += 32 * KW) { gc[d] = cen[d]; gc[CF + d] = cen[CF + d]; }
        if (wid < 2) {
            float s = 0.f;
            for (int d = lane; d < CF; d += 32) { float v = cen[wid * CF + d]; s += v * v; }
            #pragma unroll
            for (int o = 16; o; o >>= 1) s += __shfl_xor_sync(0xffffffffu, s, o);
            if (!lane) g_cnorm[bc * 2 + wid] = sqrtf(s);
        }
        __syncthreads();   // protect smem before next job
    }
}

// ---- 5. GEMM via packed f32x2 FMA: m-tile 128, 128 threads, 256 blocks (full chip) ----
#define GT 48    // k-tile
#define MT 128   // m-tile
__global__ void __launch_bounds__(128) k_gemm(const float* __restrict__ feat) {
    extern __shared__ float sm[];
    float* fS = sm;                                            // [GT][MT]
    unsigned long long* cS2 = (unsigned long long*)(sm + GT * MT);   // [NJ][GT]
    int n = blockIdx.y, m0 = blockIdx.x * MT;
    int t = threadIdx.x;
    int p = t & 63, g = t >> 6;    // p = m-pair, g = j-group (warp-uniform)
    unsigned long long acc[21];
    #pragma unroll
    for (int j = 0; j < 21; j++) acc[j] = 0ull;

    for (int k0 = 0; k0 < CF; k0 += GT) {
        __syncthreads();
        for (int idx = t; idx < GT * (MT / 4); idx += 128) {
            int dd = idx >> 5, c4 = idx & 31;
            float4 v = *(const float4*)&feat[((size_t)(n * CF + k0 + dd)) * HW + m0 + c4 * 4];
            *(float4*)&fS[dd * MT + c4 * 4] = v;
        }
        for (int idx = t; idx < NJ * GT; idx += 128) {
            int j = idx / GT, dd = idx % GT;
            float v = g_cent[((size_t)n * NJ + j) * CF + k0 + dd];
            float2 d2 = make_float2(v, v);
            cS2[j * GT + dd] = *(unsigned long long*)&d2;
        }
        __syncthreads();
        #pragma unroll 4
        for (int dd = 0; dd < GT; dd += 2) {
            unsigned long long a0 = *(const unsigned long long*)&fS[dd * MT + 2 * p];
            unsigned long long a1 = *(const unsigned long long*)&fS[(dd + 1) * MT + 2 * p];
            #pragma unroll
            for (int j = 0; j < 21; j++) {
                ulonglong2 c2 = *(const ulonglong2*)&cS2[(g * 21 + j) * GT + dd];
                FMA_F32X2(acc[j], a0, c2.x);
                FMA_F32X2(acc[j], a1, c2.y);
            }
        }
    }
    #pragma unroll
    for (int j = 0; j < 21; j++) {
        float* dp = g_D + ((size_t)n * NJ + g * 21 + j) * HW + m0;
        *(float2*)&dp[2 * p] = *(float2*)&acc[j];
    }
}

// ---- 6. fused cam + max-normalize + Sinkhorn K, vectorized (regs, no smem staging) ----
__global__ void __launch_bounds__(512) k_camkmat(const float* __restrict__ label,
                                                 float* __restrict__ out) {
    __shared__ float red[512];
    int bc = blockIdx.x, n = bc / NC, c = bc % NC, t = threadIdx.x;
    if (bc == 0 && t < NB * 2) ((int*)g_bar)[t] = 0;   // reset sinkhorn barriers each replay
    int cnt = g_cnt[bc];
    float lab = label[bc];
    float inv_cn0 = 1.f / fmaxf(g_cnorm[n * NJ + 2 * c], 1e-8f);
    float inv_cn1 = 1.f / fmaxf(g_cnorm[n * NJ + 2 * c + 1], 1e-8f);
    float ik0 = 1.f / (g_cnorm[n * NJ + c] + 1e-5f);         // kmat quirk: j = k*21 + c
    float ik1 = 1.f / (g_cnorm[n * NJ + NC + c] + 1e-5f);
    float gate = (cnt >= 2) ? 0.5f * lab : 0.f;
    const float4* D0  = (const float4*)(g_D + ((size_t)n * NJ + 2 * c) * HW);
    const float4* D1  = (const float4*)(g_D + ((size_t)n * NJ + 2 * c + 1) * HW);
    const float4* Dk0 = (const float4*)(g_D + ((size_t)n * NJ + c) * HW);
    const float4* Dk1 = (const float4*)(g_D + ((size_t)n * NJ + NC + c) * HW);
    const float4* FN  = (const float4*)(g_fnorm + n * HW);
    float4* Km4 = (float4*)(g_Kmat + (size_t)bc * HW * 2);
    float4 camv[2];
    float mx = -INFINITY;
    #pragma unroll
    for (int i = 0; i < 2; i++) {
        int f = t + i * 512;                 // float4 index (covers px 4f..4f+3)
        float4 fn = FN[f];
        float4 d0 = D0[f], d1 = D1[f], k0 = Dk0[f], k1 = Dk1[f];
        float4 cv;
        cv.x = (d0.x * inv_cn0 + d1.x * inv_cn1) * gate / fmaxf(fn.x, 1e-8f);
        cv.y = (d0.y * inv_cn0 + d1.y * inv_cn1) * gate / fmaxf(fn.y, 1e-8f);
        cv.z = (d0.z * inv_cn0 + d1.z * inv_cn1) * gate / fmaxf(fn.z, 1e-8f);
        cv.w = (d0.w * inv_cn0 + d1.w * inv_cn1) * gate / fmaxf(fn.w, 1e-8f);
        camv[i] = cv;
        mx = fmaxf(mx, fmaxf(fmaxf(cv.x, cv.y), fmaxf(cv.z, cv.w)));
        float4 ka, kb;   // interleaved [m][k]: (px0 k0, px0 k1, px1 k0, px1 k1)
        ka.x = __expf((k0.x / (fn.x + 1e-5f) * ik0 - 1.f) * 10.f);
        ka.y = __expf((k1.x / (fn.x + 1e-5f) * ik1 - 1.f) * 10.f);
        ka.z = __expf((k0.y / (fn.y + 1e-5f) * ik0 - 1.f) * 10.f);
        ka.w = __expf((k1.y / (fn.y + 1e-5f) * ik1 - 1.f) * 10.f);
        kb.x = __expf((k0.z / (fn.z + 1e-5f) * ik0 - 1.f) * 10.f);
        kb.y = __expf((k1.z / (fn.z + 1e-5f) * ik1 - 1.f) * 10.f);
        kb.z = __expf((k0.w / (fn.w + 1e-5f) * ik0 - 1.f) * 10.f);
        kb.w = __expf((k1.w / (fn.w + 1e-5f) * ik1 - 1.f) * 10.f);
        Km4[2 * f] = ka;
        Km4[2 * f + 1] = kb;
    }
    red[t] = mx;
    __syncthreads();
    for (int s = 256; s; s >>= 1) { if (t < s) red[t] = fmaxf(red[t], red[t + s]); __syncthreads(); }
    float inv = 1.f / (red[0] + 1e-5f);
    float4* O4 = (float4*)(out + (size_t)bc * HW);
    #pragma unroll
    for (int i = 0; i < 2; i++) {
        int f = t + i * 512;
        float4 cv = camv[i];
        cv.x *= inv; cv.y *= inv; cv.z *= inv; cv.w *= inv;
        O4[f] = cv;
    }
}

// ---- 7. Sinkhorn: 3 blocks per n (7 classes each), software barrier for the global
//        early-stop (err = mean over ALL classes, faithful to reference) ----
__global__ void __launch_bounds__(1024) k_sinkhorn() {
    __shared__ float cv[2 * SKC];
    __shared__ float spart[SKC][32][2];
    __shared__ float red[1024];
    __shared__ float errS;
    int blk = blockIdx.x;
    int n = blk / SKB, b = blk % SKB;
    int c0 = b * SKC;
    int t = threadIdx.x, lane = t & 31, wid = t >> 5;
    const float u = 1.f / (float)HW, v = 0.5f;
    float* rg = g_r + (size_t)n * NC * HW;
    const float4* Km4 = (const float4*)(g_Kmat + (size_t)n * NC * HW * 2);
    if (t < 2 * SKC) cv[t] = 1.f;
    for (int i = t; i < SKC * HW; i += 1024) rg[c0 * HW + i] = 1.f;
    __syncthreads();

    for (int it = 0; it < 100; it++) {
        float errp = 0.f;
        for (int cc = 0; cc < SKC; cc++) {
            int c = c0 + cc;
            float cv0 = cv[2 * cc], cv1 = cv[2 * cc + 1];
            float s0 = 0.f, s1 = 0.f;
            #pragma unroll
            for (int st = 0; st < 2; st++) {
                int i2 = t + (2 * c + st) * 1024;
                int i = 2 * i2;
                float4 kk = Km4[i2];
                float rn0 = u / (kk.x * cv0 + kk.y * cv1);
                float rn1 = u / (kk.z * cv0 + kk.w * cv1);
                errp += fabsf(rn0 - rg[i]) + fabsf(rn1 - rg[i + 1]);
                rg[i] = rn0; rg[i + 1] = rn1;
                s0 += kk.x * rn0 + kk.z * rn1;
                s1 += kk.y * rn0 + kk.w * rn1;
            }
            #pragma unroll
            for (int o = 16; o; o >>= 1) {
                s0 += __shfl_xor_sync(0xffffffffu, s0, o);
                s1 += __shfl_xor_sync(0xffffffffu, s1, o);
            }
            if (!lane) { spart[cc][wid][0] = s0; spart[cc][wid][1] = s1; }
        }
        red[t] = errp;
        __syncthreads();
        for (int s = 512; s; s >>= 1) { if (t < s) red[t] += red[t + s]; __syncthreads(); }
        if (t < 2 * SKC) {
            int cc = t >> 1, k = t & 1;
            float s = 0.f;
            #pragma unroll
            for (int w = 0; w < 32; w++) s += spart[cc][w][k];
            cv[t] = v / s;
        }
        int ph = it & 1;
        if (t == 0) {
            g_errp[n][ph][b] = red[0];
            __threadfence();
            atomicAdd(&g_bar[n][ph], 1);
            int target = SKB * ((it >> 1) + 1);   // monotonic, no resets needed
            while (atomicAdd(&g_bar[n][ph], 0) < target) { }
            __threadfence();
            errS = (g_errp[n][ph][0] + g_errp[n][ph][1] + g_errp[n][ph][2])
                   / (float)(NC * HW);
        }
        __syncthreads();
        if (errS < 0.01f) break;   // identical decision in all SKB blocks
    }
    if (t < 2 * SKC) g_cv[n * NJ + 2 * c0 + t] = cv[t];
}

// ---------------- 8. T output: vectorized elementwise r*c*K, block per (n,c) ----------------
__global__ void __launch_bounds__(512) k_tout(float* __restrict__ Tout) {
    int bc = blockIdx.x, n = bc / NC, c = bc % NC, t = threadIdx.x;
    const float4* Km4 = (const float4*)(g_Kmat + (size_t)bc * HW * 2);
    const float4* R4 = (const float4*)(g_r + (size_t)bc * HW);
    float cv0 = g_cv[n * NJ + 2 * c], cv1 = g_cv[n * NJ + 2 * c + 1];
    float4* T0 = (float4*)(Tout + (size_t)bc * 2 * HW);
    float4* T1 = T0 + HW / 4;
    #pragma unroll
    for (int i = 0; i < 2; i++) {
        int f = t + i * 512;               // float4 over r (4 px)
        float4 r4 = R4[f];
        float4 ka = Km4[2 * f], kb = Km4[2 * f + 1];
        float4 o0, o1;
        o0.x = r4.x * cv0 * ka.x;  o1.x = r4.x * cv1 * ka.y;
        o0.y = r4.y * cv0 * ka.z;  o1.y = r4.y * cv1 * ka.w;
        o0.z = r4.z * cv0 * kb.x;  o1.z = r4.z * cv1 * kb.y;
        o0.w = r4.w * cv0 * kb.z;  o1.w = r4.w * cv1 * kb.w;
        T0[f] = o0;
        T1[f] = o1;
    }
}

// ---------------- launcher ----------------
extern "C" void kernel_launch(void* const* d_in, const int* in_sizes, int n_in,
                              void* d_out, int out_size) {
    const float* norm_cam = (const float*)d_in[0];   // [8,21,64,64]
    const float* label    = (const float*)d_in[1];   // [8,21,1,1]
    const float* feature  = (const float*)d_in[2];   // [8,768,64,64]
    float* out  = (float*)d_out;                     // [8,21,64,64]
    float* Tout = out + NB * NC * HW;                // [8,21,2,64,64]

    const int KMEANS_SMEM = (2 * CF + KW * 2 * CF) * sizeof(float);      // 55296 B
    const int GEMM_SMEM   = GT * MT * 4 + NJ * GT * 8;                   // 40704 B
    cudaFuncSetAttribute(k_kmeans, cudaFuncAttributeMaxDynamicSharedMemorySize, KMEANS_SMEM);
    cudaFuncSetAttribute(k_gemm,   cudaFuncAttributeMaxDynamicSharedMemorySize, GEMM_SMEM);

    k_transpose<<<dim3(HW / 128, CF / 32, NB), 256>>>(feature);
    k_fnfin   <<<(NB * HW + 255) / 256, 256>>>();
    k_argmax  <<<(NB * HW + 255) / 256, 256>>>(norm_cam, label);
    k_lists   <<<NB * NC, 128>>>();
    k_kmeans  <<<148, 32 * KW, KMEANS_SMEM>>>();
    k_gemm    <<<dim3(HW / MT, NB), 128, GEMM_SMEM>>>(feature);
    k_camkmat <<<NB * NC, 512>>>(label, out);
    k_sinkhorn<<<NB * SKB, 1024>>>();
    k_tout    <<<NB * NC, 512>>>(Tout);
}

// round 13
// speedup vs baseline: 1.2919x; 1.0102x over previous
#include <cuda_runtime.h>
#include <math.h>

#define NB 8
#define NC 21
#define HW 4096
#define CF 768
#define NJ 42   // NC * 2
#define SKB 3   // sinkhorn blocks per image
#define SKC 7   // classes per sinkhorn block

// ---------------- scratch (__device__ globals; no allocation allowed) ----------------
__device__ float g_featT[NB * HW * CF];   // [n][m][d]
__device__ float g_fpart[24 * NB * HW];   // per-d-tile partial sumsq
__device__ float g_fnorm[NB * HW];        // ||feat[n,m]||
__device__ int   g_pcls[NB * HW];         // class of pixel if valid else -1
__device__ int   g_list[NB * NC * HW];    // valid pixel indices per (n,c), ascending
__device__ int   g_cnt[NB * NC];
__device__ float g_cent[NB * NJ * CF];    // [n][c*2+k][d]
__device__ float g_cnorm[NB * NJ];
__device__ float g_D[NB * NJ * HW];       // [n][j][m] = centers[j] . feat[m]
__device__ float g_Kmat[NB * NC * HW * 2];// [n][c][m][k]
__device__ float g_r[NB * NC * HW];
__device__ float g_cv[NB * NJ];           // sinkhorn column scalings
__device__ int   g_job;                   // kmeans work queue (reset by k_lists)
__device__ int   g_bar[NB][2];            // sinkhorn phase barriers (reset by k_camkmat)
__device__ float g_errp[NB][2][SKB];      // sinkhorn err partials, double-buffered

// packed f32x2 FMA (FFMA2): d = a*b + d, lane-wise on 2 packed floats
#define FMA_F32X2(d, a, b) \
    asm("fma.rn.f32x2 %0, %1, %2, %0;" : "+l"(d) : "l"(a), "l"(b))

// ---- 1. transpose feature (float4 both sides) + per-column partial sumsq ----
__global__ void __launch_bounds__(256) k_transpose(const float* __restrict__ feat) {
    __shared__ float tile[32][129];
    int n = blockIdx.z;
    int d0 = blockIdx.y * 32, m0 = blockIdx.x * 128;
    int t = threadIdx.x;
    #pragma unroll
    for (int i = 0; i < 4; i++) {
        int li = t + i * 256;
        int r = li >> 5, c4 = li & 31;
        float4 v = *(const float4*)&feat[((size_t)(n * CF + d0 + r)) * HW + m0 + c4 * 4];
        tile[r][c4 * 4 + 0] = v.x;
        tile[r][c4 * 4 + 1] = v.y;
        tile[r][c4 * 4 + 2] = v.z;
        tile[r][c4 * 4 + 3] = v.w;
    }
    __syncthreads();
    #pragma unroll
    for (int i = 0; i < 4; i++) {
        int li = t + i * 256;
        int m = li >> 3, d4 = li & 7;
        float4 v;
        v.x = tile[d4 * 4 + 0][m];
        v.y = tile[d4 * 4 + 1][m];
        v.z = tile[d4 * 4 + 2][m];
        v.w = tile[d4 * 4 + 3][m];
        *(float4*)&g_featT[((size_t)(n * HW + m0 + m)) * CF + d0 + d4 * 4] = v;
        float ss = v.x * v.x + v.y * v.y + v.z * v.z + v.w * v.w;
        #pragma unroll
        for (int o = 1; o < 8; o <<= 1) ss += __shfl_xor_sync(0xffffffffu, ss, o);
        if (d4 == 0) g_fpart[blockIdx.y * (NB * HW) + n * HW + m0 + m] = ss;
    }
}

// ---------------- 2. finalize feature norms (deterministic 24-way sum) ----------------
__global__ void k_fnfin() {
    int idx = blockIdx.x * blockDim.x + threadIdx.x;
    if (idx >= NB * HW) return;
    float s = 0.f;
    #pragma unroll
    for (int k = 0; k < 24; k++) s += g_fpart[k * (NB * HW) + idx];
    g_fnorm[idx] = sqrtf(s);
}

// ---------------- 3a. per-pixel argmax class, full-chip elementwise ----------------
__global__ void k_argmax(const float* __restrict__ cam, const float* __restrict__ label) {
    int idx = blockIdx.x * blockDim.x + threadIdx.x;
    if (idx >= NB * HW) return;
    int n = idx >> 12, m = idx & (HW - 1);
    const float* cp = cam + (size_t)n * NC * HW + m;
    float best = cp[0];
    int bi = 0;
    #pragma unroll
    for (int c = 1; c < NC; c++) {
        float v = cp[c * HW];
        if (v > best) { best = v; bi = c; }   // first max on ties
    }
    g_pcls[idx] = (label[n * NC + bi] > 0.f) ? bi : -1;
}

// ---- 3b. ordered compaction, block per (n,c): thread owns 32-px segment, block scan ----
__global__ void __launch_bounds__(128) k_lists() {
    __shared__ int wt[4];
    int bc = blockIdx.x, n = bc / NC, c = bc % NC, t = threadIdx.x;
    int wid = t >> 5, lane = t & 31;
    if (bc == 0 && t == 0) g_job = 0;    // reset kmeans work queue for this replay
    int4 v[8];
    const int4* pp = (const int4*)(g_pcls + (size_t)n * HW) + t * 8;
    int cnt = 0;
    #pragma unroll
    for (int i = 0; i < 8; i++) {
        v[i] = pp[i];
        cnt += (v[i].x == c) + (v[i].y == c) + (v[i].z == c) + (v[i].w == c);
    }
    int incl = cnt;
    #pragma unroll
    for (int o = 1; o < 32; o <<= 1) {
        int pv = __shfl_up_sync(0xffffffffu, incl, o);
        if (lane >= o) incl += pv;
    }
    if (lane == 31) wt[wid] = incl;
    __syncthreads();
    int woff = 0;
    #pragma unroll
    for (int w = 0; w < 4; w++) woff += (w < wid) ? wt[w] : 0;
    int off = woff + incl - cnt;         // exclusive prefix = my write offset
    int* lst = g_list + (size_t)bc * HW;
    int base = t * 32;
    #pragma unroll
    for (int i = 0; i < 8; i++) {
        if (v[i].x == c) lst[off++] = base + i * 4 + 0;
        if (v[i].y == c) lst[off++] = base + i * 4 + 1;
        if (v[i].z == c) lst[off++] = base + i * 4 + 2;
        if (v[i].w == c) lst[off++] = base + i * 4 + 3;
    }
    if (t == 0) g_cnt[bc] = wt[0] + wt[1] + wt[2] + wt[3];
}

// ---- 4. k-means: persistent work queue; smem-resident index list kills the
//         index->address L2 dependency, so the feature prefetch actually lands ----
#define KW 8   // warps per kmeans block

#define LOADPAIR(VA, VB, HAS, PI) {                                   \
    int _m0 = slst[PI];                                               \
    HAS = (PI + 1 < cnt);                                             \
    int _m1 = HAS ? slst[(PI) + 1] : _m0;                             \
    const float4* _fa = (const float4*)(fbase + (size_t)_m0 * CF) + lane; \
    const float4* _fb = (const float4*)(fbase + (size_t)_m1 * CF) + lane; \
    _Pragma("unroll")                                                 \
    for (int _j = 0; _j < 6; _j++) {                                  \
        VA[_j] = _fa[_j * 32];                                        \
        VB[_j] = _fb[_j * 32];                                        \
    } }

#define DOTPAIR(VA, VB) {                                             \
    d0a = 0.f; d1a = 0.f; d0b = 0.f; d1b = 0.f;                       \
    _Pragma("unroll")                                                 \
    for (int _j = 0; _j < 6; _j++) {                                  \
        float4 _c0 = cen4[lane + _j * 32];                            \
        float4 _c1 = cen4[48 * 4 + lane + _j * 32];                   \
        d0a += VA[_j].x * _c0.x + VA[_j].y * _c0.y                    \
             + VA[_j].z * _c0.z + VA[_j].w * _c0.w;                   \
        d1a += VA[_j].x * _c1.x + VA[_j].y * _c1.y                    \
             + VA[_j].z * _c1.z + VA[_j].w * _c1.w;                   \
        d0b += VB[_j].x * _c0.x + VB[_j].y * _c0.y                    \
             + VB[_j].z * _c0.z + VB[_j].w * _c0.w;                   \
        d1b += VB[_j].x * _c1.x + VB[_j].y * _c1.y                    \
             + VB[_j].z * _c1.z + VB[_j].w * _c1.w;                   \
    } }

#define FINPAIR(VA, VB, HAS, PI) {                                    \
    _Pragma("unroll")                                                 \
    for (int _o = 16; _o; _o >>= 1) {                                 \
        d0a += __shfl_xor_sync(0xffffffffu, d0a, _o);                 \
        d1a += __shfl_xor_sync(0xffffffffu, d1a, _o);                 \
        d0b += __shfl_xor_sync(0xffffffffu, d0b, _o);                 \
        d1b += __shfl_xor_sync(0xffffffffu, d1b, _o);                 \
    }                                                                 \
    int _aa = (d1a * inv1 > d0a * inv0) ? 1 : 0;                      \
    int _ab = (d1b * inv1 > d0b * inv0) ? 1 : 0;                      \
    if (!lane) {                                                      \
        if (iter > 0) mychg += (sprev[PI] != _aa)                     \
                             + (HAS ? (sprev[(PI) + 1] != _ab) : 0);  \
        sprev[PI] = (unsigned char)_aa;                               \
        if (HAS) sprev[(PI) + 1] = (unsigned char)_ab;                \
    }                                                                 \
    float _w0a = _aa ? 0.f : 1.f, _w1a = _aa ? 1.f : 0.f;             \
    float _w0b = 0.f, _w1b = 0.f;                                     \
    if (HAS) { _w0b = _ab ? 0.f : 1.f; _w1b = _ab ? 1.f : 0.f; }      \
    _Pragma("unroll")                                                 \
    for (int _j = 0; _j < 6; _j++) {                                  \
        acc0[_j].x = fmaf(_w0a, VA[_j].x, fmaf(_w0b, VB[_j].x, acc0[_j].x)); \
        acc0[_j].y = fmaf(_w0a, VA[_j].y, fmaf(_w0b, VB[_j].y, acc0[_j].y)); \
        acc0[_j].z = fmaf(_w0a, VA[_j].z, fmaf(_w0b, VB[_j].z, acc0[_j].z)); \
        acc0[_j].w = fmaf(_w0a, VA[_j].w, fmaf(_w0b, VB[_j].w, acc0[_j].w)); \
        acc1[_j].x = fmaf(_w1a, VA[_j].x, fmaf(_w1b, VB[_j].x, acc1[_j].x)); \
        acc1[_j].y = fmaf(_w1a, VA[_j].y, fmaf(_w1b, VB[_j].y, acc1[_j].y)); \
        acc1[_j].z = fmaf(_w1a, VA[_j].z, fmaf(_w1b, VB[_j].z, acc1[_j].z)); \
        acc1[_j].w = fmaf(_w1a, VA[_j].w, fmaf(_w1b, VB[_j].w, acc1[_j].w)); \
    }                                                                 \
    myc0 += (1 - _aa) + (HAS ? (1 - _ab) : 0);                        \
    myc1 += _aa + (HAS ? _ab : 0); }

__global__ void __launch_bounds__(32 * KW) k_kmeans() {
    extern __shared__ float buf[];
    float* cen  = buf;                     // [2][CF]
    float* part = buf + 2 * CF;            // [KW][2][CF]
    int*   slst = (int*)(buf + 2 * CF + KW * 2 * CF);   // [HW] job pixel indices
    float4* cen4 = (float4*)cen;
    __shared__ unsigned char sprev[HW];
    __shared__ int   pcnt[KW][2];
    __shared__ int   pchg[KW];
    __shared__ float inv_s[2];
    __shared__ int   cnts[2], schg, jobS;
    int t = threadIdx.x, wid = t >> 5, lane = t & 31;

    for (;;) {
        if (t == 0) jobS = atomicAdd(&g_job, 1);
        __syncthreads();
        int bc = jobS;
        __syncthreads();
        if (bc >= NB * NC) return;
        int n = bc / NC;
        int cnt = g_cnt[bc];
        float* gc = g_cent + (size_t)bc * 2 * CF;
        if (cnt < 2) {   // reference: centers forced to zero
            for (int i = t; i < 2 * CF; i += 32 * KW) gc[i] = 0.f;
            if (t < 2) g_cnorm[bc * 2 + t] = 0.f;
            __syncthreads();
            continue;
        }
        const int* lst = g_list + (size_t)bc * HW;
        const float* fbase = g_featT + (size_t)n * HW * CF;
        // stage the index list in smem: one coalesced burst, removes the
        // dependent gmem load from every pipeline step
        for (int i = t; i < cnt; i += 32 * KW) slst[i] = lst[i];
        __syncthreads();
        int i0 = slst[0], i1 = slst[1];
        for (int d = t; d < CF; d += 32 * KW) {
            cen[d]      = fbase[(size_t)i0 * CF + d];
            cen[CF + d] = fbase[(size_t)i1 * CF + d];
        }
        __syncthreads();

        for (int iter = 0; iter < 10; iter++) {
            if (wid < 2) {   // center inverse norms
                float s = 0.f;
                for (int d = lane; d < CF; d += 32) { float v = cen[wid * CF + d]; s += v * v; }
                #pragma unroll
                for (int o = 16; o; o >>= 1) s += __shfl_xor_sync(0xffffffffu, s, o);
                if (!lane) inv_s[wid] = 1.f / fmaxf(sqrtf(s), 1e-8f);
            }
            __syncthreads();
            float inv0 = inv_s[0], inv1 = inv_s[1];
            float4 acc0[6], acc1[6];
            #pragma unroll
            for (int j = 0; j < 6; j++) {
                acc0[j] = make_float4(0.f, 0.f, 0.f, 0.f);
                acc1[j] = make_float4(0.f, 0.f, 0.f, 0.f);
            }
            int myc0 = 0, myc1 = 0, mychg = 0;

            float4 vax[6], vbx[6], vay[6], vby[6];
            float d0a, d1a, d0b, d1b;
            int hasx = 0, hasy = 0;
            int pi = wid * 2;
            if (pi < cnt) LOADPAIR(vax, vbx, hasx, pi);
            while (pi < cnt) {
                int pj = pi + 2 * KW;
                if (pj < cnt) LOADPAIR(vay, vby, hasy, pj);
                DOTPAIR(vax, vbx);
                FINPAIR(vax, vbx, hasx, pi);
                pi = pj;
                if (pi >= cnt) break;
                pj = pi + 2 * KW;
                if (pj < cnt) LOADPAIR(vax, vbx, hasx, pj);
                DOTPAIR(vay, vby);
                FINPAIR(vay, vby, hasy, pi);
                pi = pj;
            }

            float4* p0 = (float4*)&part[(wid * 2 + 0) * CF];
            float4* p1 = (float4*)&part[(wid * 2 + 1) * CF];
            #pragma unroll
            for (int j = 0; j < 6; j++) {
                p0[lane + j * 32] = acc0[j];
                p1[lane + j * 32] = acc1[j];
            }
            if (!lane) { pcnt[wid][0] = myc0; pcnt[wid][1] = myc1; pchg[wid] = mychg; }
            __syncthreads();
            if (t < 2) {
                int s = 0;
                #pragma unroll
                for (int w2 = 0; w2 < KW; w2++) s += pcnt[w2][t];
                cnts[t] = s;
            }
            if (t == 2) {
                int s = 0;
                #pragma unroll
                for (int w2 = 0; w2 < KW; w2++) s += pchg[w2];
                schg = s;
            }
            __syncthreads();
            float div0 = 1.f / fmaxf((float)cnts[0], 1.f);
            float div1 = 1.f / fmaxf((float)cnts[1], 1.f);
            for (int d = t; d < CF; d += 32 * KW) {
                float s0 = 0.f, s1 = 0.f;
                #pragma unroll
                for (int w2 = 0; w2 < KW; w2++) {
                    s0 += part[(w2 * 2) * CF + d];
                    s1 += part[(w2 * 2 + 1) * CF + d];
                }
                cen[d] = s0 * div0;
                cen[CF + d] = s1 * div1;
            }
            __syncthreads();
            if (iter > 0 && schg == 0) break;   // fixed point
        }
        for (int d = t; d < CF; d += 32 * KW) { gc[d] = cen[d]; gc[CF + d] = cen[CF + d]; }
        if (wid < 2) {
            float s = 0.f;
            for (int d = lane; d < CF; d += 32) { float v = cen[wid * CF + d]; s += v * v; }
            #pragma unroll
            for (int o = 16; o; o >>= 1) s += __shfl_xor_sync(0xffffffffu, s, o);
            if (!lane) g_cnorm[bc * 2 + wid] = sqrtf(s);
        }
        __syncthreads();   // protect smem before next job
    }
}

// ---- 5. GEMM via packed f32x2 FMA: m-tile 128, 128 threads, 256 blocks (full chip) ----
#define GT 48    // k-tile
#define MT 128   // m-tile
__global__ void __launch_bounds__(128) k_gemm(const float* __restrict__ feat) {
    extern __shared__ float sm[];
    float* fS = sm;                                            // [GT][MT]
    unsigned long long* cS2 = (unsigned long long*)(sm + GT * MT);   // [NJ][GT]
    int n = blockIdx.y, m0 = blockIdx.x * MT;
    int t = threadIdx.x;
    int p = t & 63, g = t >> 6;    // p = m-pair, g = j-group (warp-uniform)
    unsigned long long acc[21];
    #pragma unroll
    for (int j = 0; j < 21; j++) acc[j] = 0ull;

    for (int k0 = 0; k0 < CF; k0 += GT) {
        __syncthreads();
        for (int idx = t; idx < GT * (MT / 4); idx += 128) {
            int dd = idx >> 5, c4 = idx & 31;
            float4 v = *(const float4*)&feat[((size_t)(n * CF + k0 + dd)) * HW + m0 + c4 * 4];
            *(float4*)&fS[dd * MT + c4 * 4] = v;
        }
        for (int idx = t; idx < NJ * GT; idx += 128) {
            int j = idx / GT, dd = idx % GT;
            float v = g_cent[((size_t)n * NJ + j) * CF + k0 + dd];
            float2 d2 = make_float2(v, v);
            cS2[j * GT + dd] = *(unsigned long long*)&d2;
        }
        __syncthreads();
        #pragma unroll 4
        for (int dd = 0; dd < GT; dd += 2) {
            unsigned long long a0 = *(const unsigned long long*)&fS[dd * MT + 2 * p];
            unsigned long long a1 = *(const unsigned long long*)&fS[(dd + 1) * MT + 2 * p];
            #pragma unroll
            for (int j = 0; j < 21; j++) {
                ulonglong2 c2 = *(const ulonglong2*)&cS2[(g * 21 + j) * GT + dd];
                FMA_F32X2(acc[j], a0, c2.x);
                FMA_F32X2(acc[j], a1, c2.y);
            }
        }
    }
    #pragma unroll
    for (int j = 0; j < 21; j++) {
        float* dp = g_D + ((size_t)n * NJ + g * 21 + j) * HW + m0;
        *(float2*)&dp[2 * p] = *(float2*)&acc[j];
    }
}

// ---- 6. fused cam + max-normalize + Sinkhorn K, vectorized (regs, no smem staging) ----
__global__ void __launch_bounds__(512) k_camkmat(const float* __restrict__ label,
                                                 float* __restrict__ out) {
    __shared__ float red[512];
    int bc = blockIdx.x, n = bc / NC, c = bc % NC, t = threadIdx.x;
    if (bc == 0 && t < NB * 2) ((int*)g_bar)[t] = 0;   // reset sinkhorn barriers each replay
    int cnt = g_cnt[bc];
    float lab = label[bc];
    float inv_cn0 = 1.f / fmaxf(g_cnorm[n * NJ + 2 * c], 1e-8f);
    float inv_cn1 = 1.f / fmaxf(g_cnorm[n * NJ + 2 * c + 1], 1e-8f);
    float ik0 = 1.f / (g_cnorm[n * NJ + c] + 1e-5f);         // kmat quirk: j = k*21 + c
    float ik1 = 1.f / (g_cnorm[n * NJ + NC + c] + 1e-5f);
    float gate = (cnt >= 2) ? 0.5f * lab : 0.f;
    const float4* D0  = (const float4*)(g_D + ((size_t)n * NJ + 2 * c) * HW);
    const float4* D1  = (const float4*)(g_D + ((size_t)n * NJ + 2 * c + 1) * HW);
    const float4* Dk0 = (const float4*)(g_D + ((size_t)n * NJ + c) * HW);
    const float4* Dk1 = (const float4*)(g_D + ((size_t)n * NJ + NC + c) * HW);
    const float4* FN  = (const float4*)(g_fnorm + n * HW);
    float4* Km4 = (float4*)(g_Kmat + (size_t)bc * HW * 2);
    float4 camv[2];
    float mx = -INFINITY;
    #pragma unroll
    for (int i = 0; i < 2; i++) {
        int f = t + i * 512;                 // float4 index (covers px 4f..4f+3)
        float4 fn = FN[f];
        float4 d0 = D0[f], d1 = D1[f], k0 = Dk0[f], k1 = Dk1[f];
        float4 cv;
        cv.x = (d0.x * inv_cn0 + d1.x * inv_cn1) * gate / fmaxf(fn.x, 1e-8f);
        cv.y = (d0.y * inv_cn0 + d1.y * inv_cn1) * gate / fmaxf(fn.y, 1e-8f);
        cv.z = (d0.z * inv_cn0 + d1.z * inv_cn1) * gate / fmaxf(fn.z, 1e-8f);
        cv.w = (d0.w * inv_cn0 + d1.w * inv_cn1) * gate / fmaxf(fn.w, 1e-8f);
        camv[i] = cv;
        mx = fmaxf(mx, fmaxf(fmaxf(cv.x, cv.y), fmaxf(cv.z, cv.w)));
        float4 ka, kb;   // interleaved [m][k]
        ka.x = __expf((k0.x / (fn.x + 1e-5f) * ik0 - 1.f) * 10.f);
        ka.y = __expf((k1.x / (fn.x + 1e-5f) * ik1 - 1.f) * 10.f);
        ka.z = __expf((k0.y / (fn.y + 1e-5f) * ik0 - 1.f) * 10.f);
        ka.w = __expf((k1.y / (fn.y + 1e-5f) * ik1 - 1.f) * 10.f);
        kb.x = __expf((k0.z / (fn.z + 1e-5f) * ik0 - 1.f) * 10.f);
        kb.y = __expf((k1.z / (fn.z + 1e-5f) * ik1 - 1.f) * 10.f);
        kb.z = __expf((k0.w / (fn.w + 1e-5f) * ik0 - 1.f) * 10.f);
        kb.w = __expf((k1.w / (fn.w + 1e-5f) * ik1 - 1.f) * 10.f);
        Km4[2 * f] = ka;
        Km4[2 * f + 1] = kb;
    }
    red[t] = mx;
    __syncthreads();
    for (int s = 256; s; s >>= 1) { if (t < s) red[t] = fmaxf(red[t], red[t + s]); __syncthreads(); }
    float inv = 1.f / (red[0] + 1e-5f);
    float4* O4 = (float4*)(out + (size_t)bc * HW);
    #pragma unroll
    for (int i = 0; i < 2; i++) {
        int f = t + i * 512;
        float4 cv = camv[i];
        cv.x *= inv; cv.y *= inv; cv.z *= inv; cv.w *= inv;
        O4[f] = cv;
    }
}

// ---- 7. Sinkhorn: 3 blocks per n (7 classes each), software barrier for the global
//        early-stop (err = mean over ALL classes, faithful to reference) ----
__global__ void __launch_bounds__(1024) k_sinkhorn() {
    __shared__ float cv[2 * SKC];
    __shared__ float spart[SKC][32][2];
    __shared__ float red[1024];
    __shared__ float errS;
    int blk = blockIdx.x;
    int n = blk / SKB, b = blk % SKB;
    int c0 = b * SKC;
    int t = threadIdx.x, lane = t & 31, wid = t >> 5;
    const float u = 1.f / (float)HW, v = 0.5f;
    float* rg = g_r + (size_t)n * NC * HW;
    const float4* Km4 = (const float4*)(g_Kmat + (size_t)n * NC * HW * 2);
    if (t < 2 * SKC) cv[t] = 1.f;
    for (int i = t; i < SKC * HW; i += 1024) rg[c0 * HW + i] = 1.f;
    __syncthreads();

    for (int it = 0; it < 100; it++) {
        float errp = 0.f;
        for (int cc = 0; cc < SKC; cc++) {
            int c = c0 + cc;
            float cv0 = cv[2 * cc], cv1 = cv[2 * cc + 1];
            float s0 = 0.f, s1 = 0.f;
            #pragma unroll
            for (int st = 0; st < 2; st++) {
                int i2 = t + (2 * c + st) * 1024;
                int i = 2 * i2;
                float4 kk = Km4[i2];
                float rn0 = u / (kk.x * cv0 + kk.y * cv1);
                float rn1 = u / (kk.z * cv0 + kk.w * cv1);
                errp += fabsf(rn0 - rg[i]) + fabsf(rn1 - rg[i + 1]);
                rg[i] = rn0; rg[i + 1] = rn1;
                s0 += kk.x * rn0 + kk.z * rn1;
                s1 += kk.y * rn0 + kk.w * rn1;
            }
            #pragma unroll
            for (int o = 16; o; o >>= 1) {
                s0 += __shfl_xor_sync(0xffffffffu, s0, o);
                s1 += __shfl_xor_sync(0xffffffffu, s1, o);
            }
            if (!lane) { spart[cc][wid][0] = s0; spart[cc][wid][1] = s1; }
        }
        red[t] = errp;
        __syncthreads();
        for (int s = 512; s; s >>= 1) { if (t < s) red[t] += red[t + s]; __syncthreads(); }
        if (t < 2 * SKC) {
            int cc = t >> 1, k = t & 1;
            float s = 0.f;
            #pragma unroll
            for (int w = 0; w < 32; w++) s += spart[cc][w][k];
            cv[t] = v / s;
        }
        int ph = it & 1;
        if (t == 0) {
            g_errp[n][ph][b] = red[0];
            __threadfence();
            atomicAdd(&g_bar[n][ph], 1);
            int target = SKB * ((it >> 1) + 1);   // monotonic, no resets needed
            while (atomicAdd(&g_bar[n][ph], 0) < target) { }
            __threadfence();
            errS = (g_errp[n][ph][0] + g_errp[n][ph][1] + g_errp[n][ph][2])
                   / (float)(NC * HW);
        }
        __syncthreads();
        if (errS < 0.01f) break;   // identical decision in all SKB blocks
    }
    if (t < 2 * SKC) g_cv[n * NJ + 2 * c0 + t] = cv[t];
}

// ---------------- 8. T output: vectorized elementwise r*c*K, block per (n,c) ----------------
__global__ void __launch_bounds__(512) k_tout(float* __restrict__ Tout) {
    int bc = blockIdx.x, n = bc / NC, c = bc % NC, t = threadIdx.x;
    const float4* Km4 = (const float4*)(g_Kmat + (size_t)bc * HW * 2);
    const float4* R4 = (const float4*)(g_r + (size_t)bc * HW);
    float cv0 = g_cv[n * NJ + 2 * c], cv1 = g_cv[n * NJ + 2 * c + 1];
    float4* T0 = (float4*)(Tout + (size_t)bc * 2 * HW);
    float4* T1 = T0 + HW / 4;
    #pragma unroll
    for (int i = 0; i < 2; i++) {
        int f = t + i * 512;
        float4 r4 = R4[f];
        float4 ka = Km4[2 * f], kb = Km4[2 * f + 1];
        float4 o0, o1;
        o0.x = r4.x * cv0 * ka.x;  o1.x = r4.x * cv1 * ka.y;
        o0.y = r4.y * cv0 * ka.z;  o1.y = r4.y * cv1 * ka.w;
        o0.z = r4.z * cv0 * kb.x;  o1.z = r4.z * cv1 * kb.y;
        o0.w = r4.w * cv0 * kb.z;  o1.w = r4.w * cv1 * kb.w;
        T0[f] = o0;
        T1[f] = o1;
    }
}

// ---------------- launcher ----------------
extern "C" void kernel_launch(void* const* d_in, const int* in_sizes, int n_in,
                              void* d_out, int out_size) {
    const float* norm_cam = (const float*)d_in[0];   // [8,21,64,64]
    const float* label    = (const float*)d_in[1];   // [8,21,1,1]
    const float* feature  = (const float*)d_in[2];   // [8,768,64,64]
    float* out  = (float*)d_out;                     // [8,21,64,64]
    float* Tout = out + NB * NC * HW;                // [8,21,2,64,64]

    const int KMEANS_SMEM = (2 * CF + KW * 2 * CF) * sizeof(float) + HW * 4;  // 71680 B
    const int GEMM_SMEM   = GT * MT * 4 + NJ * GT * 8;                        // 40704 B
    cudaFuncSetAttribute(k_kmeans, cudaFuncAttributeMaxDynamicSharedMemorySize, KMEANS_SMEM);
    cudaFuncSetAttribute(k_gemm,   cudaFuncAttributeMaxDynamicSharedMemorySize, GEMM_SMEM);

    k_transpose<<<dim3(HW / 128, CF / 32, NB), 256>>>(feature);
    k_fnfin   <<<(NB * HW + 255) / 256, 256>>>();
    k_argmax  <<<(NB * HW + 255) / 256, 256>>>(norm_cam, label);
    k_lists   <<<NB * NC, 128>>>();
    k_kmeans  <<<148, 32 * KW, KMEANS_SMEM>>>();
    k_gemm    <<<dim3(HW / MT, NB), 128, GEMM_SMEM>>>(feature);
    k_camkmat <<<NB * NC, 512>>>(label, out);
    k_sinkhorn<<<NB * SKB, 1024>>>();
    k_tout    <<<NB * NC, 512>>>(Tout);
}

// round 14
// speedup vs baseline: 1.3151x; 1.0180x over previous
#include <cuda_runtime.h>
#include <math.h>

#define NB 8
#define NC 21
#define HW 4096
#define CF 768
#define NJ 42   // NC * 2
#define SKB 3   // (legacy constant, barrier array sizing)
#define SCH 8   // sinkhorn speculative chunk length

// ---------------- scratch (__device__ globals; no allocation allowed) ----------------
__device__ float g_featT[NB * HW * CF];   // [n][m][d]
__device__ float g_fpart[24 * NB * HW];   // per-d-tile partial sumsq
__device__ float g_fnorm[NB * HW];        // ||feat[n,m]||
__device__ int   g_pcls[NB * HW];         // class of pixel if valid else -1
__device__ int   g_list[NB * NC * HW];    // valid pixel indices per (n,c), ascending
__device__ int   g_cnt[NB * NC];
__device__ float g_cent[NB * NJ * CF];    // [n][c*2+k][d]
__device__ float g_cnorm[NB * NJ];
__device__ float g_D[NB * NJ * HW];       // [n][j][m] = centers[j] . feat[m]
__device__ float g_Kmat[NB * NC * HW * 2];// [n][c][m][k]
__device__ float g_r[NB * NC * HW];
__device__ float g_cv[NB * NJ];           // sinkhorn column scalings
__device__ int   g_job;                   // kmeans work queue (reset by k_lists)
__device__ int   g_bar[NB][2];            // sinkhorn chunk barriers (reset by k_camkmat)
__device__ float g_errt[NB * NC][112];    // per-class per-iteration err partials

// packed f32x2 FMA (FFMA2): d = a*b + d, lane-wise on 2 packed floats
#define FMA_F32X2(d, a, b) \
    asm("fma.rn.f32x2 %0, %1, %2, %0;" : "+l"(d) : "l"(a), "l"(b))

// ---- 1. transpose feature (float4 both sides) + per-column partial sumsq ----
__global__ void __launch_bounds__(256) k_transpose(const float* __restrict__ feat) {
    __shared__ float tile[32][129];
    int n = blockIdx.z;
    int d0 = blockIdx.y * 32, m0 = blockIdx.x * 128;
    int t = threadIdx.x;
    #pragma unroll
    for (int i = 0; i < 4; i++) {
        int li = t + i * 256;
        int r = li >> 5, c4 = li & 31;
        float4 v = *(const float4*)&feat[((size_t)(n * CF + d0 + r)) * HW + m0 + c4 * 4];
        tile[r][c4 * 4 + 0] = v.x;
        tile[r][c4 * 4 + 1] = v.y;
        tile[r][c4 * 4 + 2] = v.z;
        tile[r][c4 * 4 + 3] = v.w;
    }
    __syncthreads();
    #pragma unroll
    for (int i = 0; i < 4; i++) {
        int li = t + i * 256;
        int m = li >> 3, d4 = li & 7;
        float4 v;
        v.x = tile[d4 * 4 + 0][m];
        v.y = tile[d4 * 4 + 1][m];
        v.z = tile[d4 * 4 + 2][m];
        v.w = tile[d4 * 4 + 3][m];
        *(float4*)&g_featT[((size_t)(n * HW + m0 + m)) * CF + d0 + d4 * 4] = v;
        float ss = v.x * v.x + v.y * v.y + v.z * v.z + v.w * v.w;
        #pragma unroll
        for (int o = 1; o < 8; o <<= 1) ss += __shfl_xor_sync(0xffffffffu, ss, o);
        if (d4 == 0) g_fpart[blockIdx.y * (NB * HW) + n * HW + m0 + m] = ss;
    }
}

// ---------------- 2. finalize feature norms (deterministic 24-way sum) ----------------
__global__ void k_fnfin() {
    int idx = blockIdx.x * blockDim.x + threadIdx.x;
    if (idx >= NB * HW) return;
    float s = 0.f;
    #pragma unroll
    for (int k = 0; k < 24; k++) s += g_fpart[k * (NB * HW) + idx];
    g_fnorm[idx] = sqrtf(s);
}

// ---------------- 3a. per-pixel argmax class, full-chip elementwise ----------------
__global__ void k_argmax(const float* __restrict__ cam, const float* __restrict__ label) {
    int idx = blockIdx.x * blockDim.x + threadIdx.x;
    if (idx >= NB * HW) return;
    int n = idx >> 12, m = idx & (HW - 1);
    const float* cp = cam + (size_t)n * NC * HW + m;
    float best = cp[0];
    int bi = 0;
    #pragma unroll
    for (int c = 1; c < NC; c++) {
        float v = cp[c * HW];
        if (v > best) { best = v; bi = c; }   // first max on ties
    }
    g_pcls[idx] = (label[n * NC + bi] > 0.f) ? bi : -1;
}

// ---- 3b. ordered compaction, block per (n,c): thread owns 32-px segment, block scan ----
__global__ void __launch_bounds__(128) k_lists() {
    __shared__ int wt[4];
    int bc = blockIdx.x, n = bc / NC, c = bc % NC, t = threadIdx.x;
    int wid = t >> 5, lane = t & 31;
    if (bc == 0 && t == 0) g_job = 0;    // reset kmeans work queue for this replay
    int4 v[8];
    const int4* pp = (const int4*)(g_pcls + (size_t)n * HW) + t * 8;
    int cnt = 0;
    #pragma unroll
    for (int i = 0; i < 8; i++) {
        v[i] = pp[i];
        cnt += (v[i].x == c) + (v[i].y == c) + (v[i].z == c) + (v[i].w == c);
    }
    int incl = cnt;
    #pragma unroll
    for (int o = 1; o < 32; o <<= 1) {
        int pv = __shfl_up_sync(0xffffffffu, incl, o);
        if (lane >= o) incl += pv;
    }
    if (lane == 31) wt[wid] = incl;
    __syncthreads();
    int woff = 0;
    #pragma unroll
    for (int w = 0; w < 4; w++) woff += (w < wid) ? wt[w] : 0;
    int off = woff + incl - cnt;         // exclusive prefix = my write offset
    int* lst = g_list + (size_t)bc * HW;
    int base = t * 32;
    #pragma unroll
    for (int i = 0; i < 8; i++) {
        if (v[i].x == c) lst[off++] = base + i * 4 + 0;
        if (v[i].y == c) lst[off++] = base + i * 4 + 1;
        if (v[i].z == c) lst[off++] = base + i * 4 + 2;
        if (v[i].w == c) lst[off++] = base + i * 4 + 3;
    }
    if (t == 0) g_cnt[bc] = wt[0] + wt[1] + wt[2] + wt[3];
}

// ---- 4. k-means: persistent work queue; smem index list; 2-px pipelined; early-exit ----
#define KW 8   // warps per kmeans block

#define LOADPAIR(VA, VB, HAS, PI) {                                   \
    int _m0 = slst[PI];                                               \
    HAS = (PI + 1 < cnt);                                             \
    int _m1 = HAS ? slst[(PI) + 1] : _m0;                             \
    const float4* _fa = (const float4*)(fbase + (size_t)_m0 * CF) + lane; \
    const float4* _fb = (const float4*)(fbase + (size_t)_m1 * CF) + lane; \
    _Pragma("unroll")                                                 \
    for (int _j = 0; _j < 6; _j++) {                                  \
        VA[_j] = _fa[_j * 32];                                        \
        VB[_j] = _fb[_j * 32];                                        \
    } }

#define DOTPAIR(VA, VB) {                                             \
    d0a = 0.f; d1a = 0.f; d0b = 0.f; d1b = 0.f;                       \
    _Pragma("unroll")                                                 \
    for (int _j = 0; _j < 6; _j++) {                                  \
        float4 _c0 = cen4[lane + _j * 32];                            \
        float4 _c1 = cen4[48 * 4 + lane + _j * 32];                   \
        d0a += VA[_j].x * _c0.x + VA[_j].y * _c0.y                    \
             + VA[_j].z * _c0.z + VA[_j].w * _c0.w;                   \
        d1a += VA[_j].x * _c1.x + VA[_j].y * _c1.y                    \
             + VA[_j].z * _c1.z + VA[_j].w * _c1.w;                   \
        d0b += VB[_j].x * _c0.x + VB[_j].y * _c0.y                    \
             + VB[_j].z * _c0.z + VB[_j].w * _c0.w;                   \
        d1b += VB[_j].x * _c1.x + VB[_j].y * _c1.y                    \
             + VB[_j].z * _c1.z + VB[_j].w * _c1.w;                   \
    } }

#define FINPAIR(VA, VB, HAS, PI) {                                    \
    _Pragma("unroll")                                                 \
    for (int _o = 16; _o; _o >>= 1) {                                 \
        d0a += __shfl_xor_sync(0xffffffffu, d0a, _o);                 \
        d1a += __shfl_xor_sync(0xffffffffu, d1a, _o);                 \
        d0b += __shfl_xor_sync(0xffffffffu, d0b, _o);                 \
        d1b += __shfl_xor_sync(0xffffffffu, d1b, _o);                 \
    }                                                                 \
    int _aa = (d1a * inv1 > d0a * inv0) ? 1 : 0;                      \
    int _ab = (d1b * inv1 > d0b * inv0) ? 1 : 0;                      \
    if (!lane) {                                                      \
        if (iter > 0) mychg += (sprev[PI] != _aa)                     \
                             + (HAS ? (sprev[(PI) + 1] != _ab) : 0);  \
        sprev[PI] = (unsigned char)_aa;                               \
        if (HAS) sprev[(PI) + 1] = (unsigned char)_ab;                \
    }                                                                 \
    float _w0a = _aa ? 0.f : 1.f, _w1a = _aa ? 1.f : 0.f;             \
    float _w0b = 0.f, _w1b = 0.f;                                     \
    if (HAS) { _w0b = _ab ? 0.f : 1.f; _w1b = _ab ? 1.f : 0.f; }      \
    _Pragma("unroll")                                                 \
    for (int _j = 0; _j < 6; _j++) {                                  \
        acc0[_j].x = fmaf(_w0a, VA[_j].x, fmaf(_w0b, VB[_j].x, acc0[_j].x)); \
        acc0[_j].y = fmaf(_w0a, VA[_j].y, fmaf(_w0b, VB[_j].y, acc0[_j].y)); \
        acc0[_j].z = fmaf(_w0a, VA[_j].z, fmaf(_w0b, VB[_j].z, acc0[_j].z)); \
        acc0[_j].w = fmaf(_w0a, VA[_j].w, fmaf(_w0b, VB[_j].w, acc0[_j].w)); \
        acc1[_j].x = fmaf(_w1a, VA[_j].x, fmaf(_w1b, VB[_j].x, acc1[_j].x)); \
        acc1[_j].y = fmaf(_w1a, VA[_j].y, fmaf(_w1b, VB[_j].y, acc1[_j].y)); \
        acc1[_j].z = fmaf(_w1a, VA[_j].z, fmaf(_w1b, VB[_j].z, acc1[_j].z)); \
        acc1[_j].w = fmaf(_w1a, VA[_j].w, fmaf(_w1b, VB[_j].w, acc1[_j].w)); \
    }                                                                 \
    myc0 += (1 - _aa) + (HAS ? (1 - _ab) : 0);                        \
    myc1 += _aa + (HAS ? _ab : 0); }

__global__ void __launch_bounds__(32 * KW) k_kmeans() {
    extern __shared__ float buf[];
    float* cen  = buf;                     // [2][CF]
    float* part = buf + 2 * CF;            // [KW][2][CF]
    int*   slst = (int*)(buf + 2 * CF + KW * 2 * CF);   // [HW] job pixel indices
    float4* cen4 = (float4*)cen;
    __shared__ unsigned char sprev[HW];
    __shared__ int   pcnt[KW][2];
    __shared__ int   pchg[KW];
    __shared__ float inv_s[2];
    __shared__ int   cnts[2], schg, jobS;
    int t = threadIdx.x, wid = t >> 5, lane = t & 31;

    for (;;) {
        if (t == 0) jobS = atomicAdd(&g_job, 1);
        __syncthreads();
        int bc = jobS;
        __syncthreads();
        if (bc >= NB * NC) return;
        int n = bc / NC;
        int cnt = g_cnt[bc];
        float* gc = g_cent + (size_t)bc * 2 * CF;
        if (cnt < 2) {   // reference: centers forced to zero
            for (int i = t; i < 2 * CF; i += 32 * KW) gc[i] = 0.f;
            if (t < 2) g_cnorm[bc * 2 + t] = 0.f;
            __syncthreads();
            continue;
        }
        const int* lst = g_list + (size_t)bc * HW;
        const float* fbase = g_featT + (size_t)n * HW * CF;
        for (int i = t; i < cnt; i += 32 * KW) slst[i] = lst[i];
        __syncthreads();
        int i0 = slst[0], i1 = slst[1];
        for (int d = t; d < CF; d += 32 * KW) {
            cen[d]      = fbase[(size_t)i0 * CF + d];
            cen[CF + d] = fbase[(size_t)i1 * CF + d];
        }
        __syncthreads();

        for (int iter = 0; iter < 10; iter++) {
            if (wid < 2) {   // center inverse norms
                float s = 0.f;
                for (int d = lane; d < CF; d += 32) { float v = cen[wid * CF + d]; s += v * v; }
                #pragma unroll
                for (int o = 16; o; o >>= 1) s += __shfl_xor_sync(0xffffffffu, s, o);
                if (!lane) inv_s[wid] = 1.f / fmaxf(sqrtf(s), 1e-8f);
            }
            __syncthreads();
            float inv0 = inv_s[0], inv1 = inv_s[1];
            float4 acc0[6], acc1[6];
            #pragma unroll
            for (int j = 0; j < 6; j++) {
                acc0[j] = make_float4(0.f, 0.f, 0.f, 0.f);
                acc1[j] = make_float4(0.f, 0.f, 0.f, 0.f);
            }
            int myc0 = 0, myc1 = 0, mychg = 0;

            float4 vax[6], vbx[6], vay[6], vby[6];
            float d0a, d1a, d0b, d1b;
            int hasx = 0, hasy = 0;
            int pi = wid * 2;
            if (pi < cnt) LOADPAIR(vax, vbx, hasx, pi);
            while (pi < cnt) {
                int pj = pi + 2 * KW;
                if (pj < cnt) LOADPAIR(vay, vby, hasy, pj);
                DOTPAIR(vax, vbx);
                FINPAIR(vax, vbx, hasx, pi);
                pi = pj;
                if (pi >= cnt) break;
                pj = pi + 2 * KW;
                if (pj < cnt) LOADPAIR(vax, vbx, hasx, pj);
                DOTPAIR(vay, vby);
                FINPAIR(vay, vby, hasy, pi);
                pi = pj;
            }

            float4* p0 = (float4*)&part[(wid * 2 + 0) * CF];
            float4* p1 = (float4*)&part[(wid * 2 + 1) * CF];
            #pragma unroll
            for (int j = 0; j < 6; j++) {
                p0[lane + j * 32] = acc0[j];
                p1[lane + j * 32] = acc1[j];
            }
            if (!lane) { pcnt[wid][0] = myc0; pcnt[wid][1] = myc1; pchg[wid] = mychg; }
            __syncthreads();
            if (t < 2) {
                int s = 0;
                #pragma unroll
                for (int w2 = 0; w2 < KW; w2++) s += pcnt[w2][t];
                cnts[t] = s;
            }
            if (t == 2) {
                int s = 0;
                #pragma unroll
                for (int w2 = 0; w2 < KW; w2++) s += pchg[w2];
                schg = s;
            }
            __syncthreads();
            float div0 = 1.f / fmaxf((float)cnts[0], 1.f);
            float div1 = 1.f / fmaxf((float)cnts[1], 1.f);
            for (int d = t; d < CF; d += 32 * KW) {
                float s0 = 0.f, s1 = 0.f;
                #pragma unroll
                for (int w2 = 0; w2 < KW; w2++) {
                    s0 += part[(w2 * 2) * CF + d];
                    s1 += part[(w2 * 2 + 1) * CF + d];
                }
                cen[d] = s0 * div0;
                cen[CF + d] = s1 * div1;
            }
            __syncthreads();
            if (iter > 0 && schg == 0) break;   // fixed point
        }
        for (int d = t; d < CF; d += 32 * KW) { gc[d] = cen[d]; gc[CF + d] = cen[CF + d]; }
        if (wid < 2) {
            float s = 0.f;
            for (int d = lane; d < CF; d += 32) { float v = cen[wid * CF + d]; s += v * v; }
            #pragma unroll
            for (int o = 16; o; o >>= 1) s += __shfl_xor_sync(0xffffffffu, s, o);
            if (!lane) g_cnorm[bc * 2 + wid] = sqrtf(s);
        }
        __syncthreads();   // protect smem before next job
    }
}

// ---- 5. GEMM via packed f32x2 FMA: m-tile 128, 128 threads, 256 blocks (full chip) ----
#define GT 48    // k-tile
#define MT 128   // m-tile
__global__ void __launch_bounds__(128) k_gemm(const float* __restrict__ feat) {
    extern __shared__ float sm[];
    float* fS = sm;                                            // [GT][MT]
    unsigned long long* cS2 = (unsigned long long*)(sm + GT * MT);   // [NJ][GT]
    int n = blockIdx.y, m0 = blockIdx.x * MT;
    int t = threadIdx.x;
    int p = t & 63, g = t >> 6;    // p = m-pair, g = j-group (warp-uniform)
    unsigned long long acc[21];
    #pragma unroll
    for (int j = 0; j < 21; j++) acc[j] = 0ull;

    for (int k0 = 0; k0 < CF; k0 += GT) {
        __syncthreads();
        for (int idx = t; idx < GT * (MT / 4); idx += 128) {
            int dd = idx >> 5, c4 = idx & 31;
            float4 v = *(const float4*)&feat[((size_t)(n * CF + k0 + dd)) * HW + m0 + c4 * 4];
            *(float4*)&fS[dd * MT + c4 * 4] = v;
        }
        for (int idx = t; idx < NJ * GT; idx += 128) {
            int j = idx / GT, dd = idx % GT;
            float v = g_cent[((size_t)n * NJ + j) * CF + k0 + dd];
            float2 d2 = make_float2(v, v);
            cS2[j * GT + dd] = *(unsigned long long*)&d2;
        }
        __syncthreads();
        #pragma unroll 4
        for (int dd = 0; dd < GT; dd += 2) {
            unsigned long long a0 = *(const unsigned long long*)&fS[dd * MT + 2 * p];
            unsigned long long a1 = *(const unsigned long long*)&fS[(dd + 1) * MT + 2 * p];
            #pragma unroll
            for (int j = 0; j < 21; j++) {
                ulonglong2 c2 = *(const ulonglong2*)&cS2[(g * 21 + j) * GT + dd];
                FMA_F32X2(acc[j], a0, c2.x);
                FMA_F32X2(acc[j], a1, c2.y);
            }
        }
    }
    #pragma unroll
    for (int j = 0; j < 21; j++) {
        float* dp = g_D + ((size_t)n * NJ + g * 21 + j) * HW + m0;
        *(float2*)&dp[2 * p] = *(float2*)&acc[j];
    }
}

// ---- 6. fused cam + max-normalize + Sinkhorn K, vectorized (regs, no smem staging) ----
__global__ void __launch_bounds__(512) k_camkmat(const float* __restrict__ label,
                                                 float* __restrict__ out) {
    __shared__ float red[512];
    int bc = blockIdx.x, n = bc / NC, c = bc % NC, t = threadIdx.x;
    if (bc == 0 && t < NB * 2) ((int*)g_bar)[t] = 0;   // reset sinkhorn barriers each replay
    int cnt = g_cnt[bc];
    float lab = label[bc];
    float inv_cn0 = 1.f / fmaxf(g_cnorm[n * NJ + 2 * c], 1e-8f);
    float inv_cn1 = 1.f / fmaxf(g_cnorm[n * NJ + 2 * c + 1], 1e-8f);
    float ik0 = 1.f / (g_cnorm[n * NJ + c] + 1e-5f);         // kmat quirk: j = k*21 + c
    float ik1 = 1.f / (g_cnorm[n * NJ + NC + c] + 1e-5f);
    float gate = (cnt >= 2) ? 0.5f * lab : 0.f;
    const float4* D0  = (const float4*)(g_D + ((size_t)n * NJ + 2 * c) * HW);
    const float4* D1  = (const float4*)(g_D + ((size_t)n * NJ + 2 * c + 1) * HW);
    const float4* Dk0 = (const float4*)(g_D + ((size_t)n * NJ + c) * HW);
    const float4* Dk1 = (const float4*)(g_D + ((size_t)n * NJ + NC + c) * HW);
    const float4* FN  = (const float4*)(g_fnorm + n * HW);
    float4* Km4 = (float4*)(g_Kmat + (size_t)bc * HW * 2);
    float4 camv[2];
    float mx = -INFINITY;
    #pragma unroll
    for (int i = 0; i < 2; i++) {
        int f = t + i * 512;                 // float4 index (covers px 4f..4f+3)
        float4 fn = FN[f];
        float4 d0 = D0[f], d1 = D1[f], k0 = Dk0[f], k1 = Dk1[f];
        float4 cv;
        cv.x = (d0.x * inv_cn0 + d1.x * inv_cn1) * gate / fmaxf(fn.x, 1e-8f);
        cv.y = (d0.y * inv_cn0 + d1.y * inv_cn1) * gate / fmaxf(fn.y, 1e-8f);
        cv.z = (d0.z * inv_cn0 + d1.z * inv_cn1) * gate / fmaxf(fn.z, 1e-8f);
        cv.w = (d0.w * inv_cn0 + d1.w * inv_cn1) * gate / fmaxf(fn.w, 1e-8f);
        camv[i] = cv;
        mx = fmaxf(mx, fmaxf(fmaxf(cv.x, cv.y), fmaxf(cv.z, cv.w)));
        float4 ka, kb;   // interleaved [m][k]
        ka.x = __expf((k0.x / (fn.x + 1e-5f) * ik0 - 1.f) * 10.f);
        ka.y = __expf((k1.x / (fn.x + 1e-5f) * ik1 - 1.f) * 10.f);
        ka.z = __expf((k0.y / (fn.y + 1e-5f) * ik0 - 1.f) * 10.f);
        ka.w = __expf((k1.y / (fn.y + 1e-5f) * ik1 - 1.f) * 10.f);
        kb.x = __expf((k0.z / (fn.z + 1e-5f) * ik0 - 1.f) * 10.f);
        kb.y = __expf((k1.z / (fn.z + 1e-5f) * ik1 - 1.f) * 10.f);
        kb.z = __expf((k0.w / (fn.w + 1e-5f) * ik0 - 1.f) * 10.f);
        kb.w = __expf((k1.w / (fn.w + 1e-5f) * ik1 - 1.f) * 10.f);
        Km4[2 * f] = ka;
        Km4[2 * f + 1] = kb;
    }
    red[t] = mx;
    __syncthreads();
    for (int s = 256; s; s >>= 1) { if (t < s) red[t] = fmaxf(red[t], red[t + s]); __syncthreads(); }
    float inv = 1.f / (red[0] + 1e-5f);
    float4* O4 = (float4*)(out + (size_t)bc * HW);
    #pragma unroll
    for (int i = 0; i < 2; i++) {
        int f = t + i * 512;
        float4 cv = camv[i];
        cv.x *= inv; cv.y *= inv; cv.z *= inv; cv.w *= inv;
        O4[f] = cv;
    }
}

// ---- 7. Sinkhorn: block per (n,c), r in registers, cv trajectory in smem,
//        speculative chunks of SCH iterations + one cross-block barrier per chunk.
//        Global early-stop T determined from deterministic fixed-order err table;
//        final r_T rolled forward exactly from cv[T-1] (bit-identical expression) ----
__global__ void __launch_bounds__(256) k_sinkhorn() {
    __shared__ float cvh[112][2];     // cv trajectory (after each body)
    __shared__ float partE[8], partA[8], partB[8];
    __shared__ int   shT;
    int bc = blockIdx.x, n = bc / NC;
    int t = threadIdx.x, lane = t & 31, wid = t >> 5;
    const float u = 1.f / (float)HW, v = 0.5f;
    const float4* Km4 = (const float4*)(g_Kmat + (size_t)bc * HW * 2);
    float rp[16];                      // current r (16 px per thread)
    #pragma unroll
    for (int j = 0; j < 16; j++) rp[j] = 1.f;
    float cv0 = 1.f, cv1 = 1.f;
    int T = -1;

    for (int chunk = 0; chunk < 100; chunk += SCH) {
        int cend = chunk + SCH; if (cend > 100) cend = 100;
        for (int it = chunk; it < cend; it++) {
            float errp = 0.f, s0 = 0.f, s1 = 0.f;
            #pragma unroll
            for (int st = 0; st < 8; st++) {
                float4 kk = Km4[t + st * 256];         // px pair (2i2, 2i2+1)
                float rn0 = u / (kk.x * cv0 + kk.y * cv1);
                float rn1 = u / (kk.z * cv0 + kk.w * cv1);
                errp += fabsf(rn0 - rp[2 * st]) + fabsf(rn1 - rp[2 * st + 1]);
                rp[2 * st] = rn0; rp[2 * st + 1] = rn1;
                s0 += kk.x * rn0 + kk.z * rn1;
                s1 += kk.y * rn0 + kk.w * rn1;
            }
            #pragma unroll
            for (int o = 16; o; o >>= 1) {
                errp += __shfl_xor_sync(0xffffffffu, errp, o);
                s0   += __shfl_xor_sync(0xffffffffu, s0, o);
                s1   += __shfl_xor_sync(0xffffffffu, s1, o);
            }
            if (!lane) { partE[wid] = errp; partA[wid] = s0; partB[wid] = s1; }
            __syncthreads();
            if (t == 0) {
                float e = 0.f, a = 0.f, b = 0.f;
                #pragma unroll
                for (int w = 0; w < 8; w++) { e += partE[w]; a += partA[w]; b += partB[w]; }
                g_errt[bc][it] = e;
                cvh[it][0] = v / a;
                cvh[it][1] = v / b;
            }
            __syncthreads();
            cv0 = cvh[it][0]; cv1 = cvh[it][1];
        }
        // cross-block barrier (21 class-blocks of this n), monotonic counter
        if (t == 0) {
            __threadfence();
            atomicAdd(&g_bar[n][0], 1);
            int target = NC * (chunk / SCH + 1);
            while (atomicAdd(&g_bar[n][0], 0) < target) { }
            __threadfence();
            // deterministic: first it in chunk with global mean err < 0.01
            int Tf = -1;
            for (int i2 = chunk; i2 < cend && Tf < 0; i2++) {
                float es = 0.f;
                for (int cc = 0; cc < NC; cc++) es += g_errt[n * NC + cc][i2];
                if (es / (float)(NC * HW) < 0.01f) Tf = i2;
            }
            shT = Tf;
        }
        __syncthreads();
        if (shT >= 0) { T = shT; break; }
    }
    if (T < 0) T = 99;
    // rollforward: r_T = u / (K @ cv[T-1]); identical expression -> identical bits
    float c0p = (T == 0) ? 1.f : cvh[T - 1][0];
    float c1p = (T == 0) ? 1.f : cvh[T - 1][1];
    float2* rg2 = (float2*)(g_r + (size_t)bc * HW);
    #pragma unroll
    for (int st = 0; st < 8; st++) {
        int f = t + st * 256;
        float4 kk = Km4[f];
        float2 rr;
        rr.x = u / (kk.x * c0p + kk.y * c1p);
        rr.y = u / (kk.z * c0p + kk.w * c1p);
        rg2[f] = rr;
    }
    if (t == 0) {
        g_cv[n * NJ + 2 * (bc % NC) + 0] = cvh[T][0];
        g_cv[n * NJ + 2 * (bc % NC) + 1] = cvh[T][1];
    }
}

// ---------------- 8. T output: vectorized elementwise r*c*K, block per (n,c) ----------------
__global__ void __launch_bounds__(512) k_tout(float* __restrict__ Tout) {
    int bc = blockIdx.x, n = bc / NC, c = bc % NC, t = threadIdx.x;
    const float4* Km4 = (const float4*)(g_Kmat + (size_t)bc * HW * 2);
    const float4* R4 = (const float4*)(g_r + (size_t)bc * HW);
    float cv0 = g_cv[n * NJ + 2 * c], cv1 = g_cv[n * NJ + 2 * c + 1];
    float4* T0 = (float4*)(Tout + (size_t)bc * 2 * HW);
    float4* T1 = T0 + HW / 4;
    #pragma unroll
    for (int i = 0; i < 2; i++) {
        int f = t + i * 512;
        float4 r4 = R4[f];
        float4 ka = Km4[2 * f], kb = Km4[2 * f + 1];
        float4 o0, o1;
        o0.x = r4.x * cv0 * ka.x;  o1.x = r4.x * cv1 * ka.y;
        o0.y = r4.y * cv0 * ka.z;  o1.y = r4.y * cv1 * ka.w;
        o0.z = r4.z * cv0 * kb.x;  o1.z = r4.z * cv1 * kb.y;
        o0.w = r4.w * cv0 * kb.z;  o1.w = r4.w * cv1 * kb.w;
        T0[f] = o0;
        T1[f] = o1;
    }
}

// ---------------- launcher ----------------
extern "C" void kernel_launch(void* const* d_in, const int* in_sizes, int n_in,
                              void* d_out, int out_size) {
    const float* norm_cam = (const float*)d_in[0];   // [8,21,64,64]
    const float* label    = (const float*)d_in[1];   // [8,21,1,1]
    const float* feature  = (const float*)d_in[2];   // [8,768,64,64]
    float* out  = (float*)d_out;                     // [8,21,64,64]
    float* Tout = out + NB * NC * HW;                // [8,21,2,64,64]

    const int KMEANS_SMEM = (2 * CF + KW * 2 * CF) * sizeof(float) + HW * 4;  // 71680 B
    const int GEMM_SMEM   = GT * MT * 4 + NJ * GT * 8;                        // 40704 B
    cudaFuncSetAttribute(k_kmeans, cudaFuncAttributeMaxDynamicSharedMemorySize, KMEANS_SMEM);
    cudaFuncSetAttribute(k_gemm,   cudaFuncAttributeMaxDynamicSharedMemorySize, GEMM_SMEM);

    k_transpose<<<dim3(HW / 128, CF / 32, NB), 256>>>(feature);
    k_fnfin   <<<(NB * HW + 255) / 256, 256>>>();
    k_argmax  <<<(NB * HW + 255) / 256, 256>>>(norm_cam, label);
    k_lists   <<<NB * NC, 128>>>();
    k_kmeans  <<<148, 32 * KW, KMEANS_SMEM>>>();
    k_gemm    <<<dim3(HW / MT, NB), 128, GEMM_SMEM>>>(feature);
    k_camkmat <<<NB * NC, 512>>>(label, out);
    k_sinkhorn<<<NB * NC, 256>>>();
    k_tout    <<<NB * NC, 512>>>(Tout);
}

// round 15
// speedup vs baseline: 1.3344x; 1.0146x over previous
#include <cuda_runtime.h>
#include <math.h>

#define NB 8
#define NC 21
#define HW 4096
#define CF 768
#define NJ 42   // NC * 2
#define SCH 8   // sinkhorn speculative chunk length

// ---------------- scratch (__device__ globals; no allocation allowed) ----------------
__device__ float g_featT[NB * HW * CF];   // [n][m][d]
__device__ float g_fpart[24 * NB * HW];   // per-d-tile partial sumsq
__device__ float g_fnorm[NB * HW];        // ||feat[n,m]||
__device__ int   g_pcls[NB * HW];         // class of pixel if valid else -1
__device__ int   g_list[NB * NC * HW];    // valid pixel indices per (n,c), ascending
__device__ int   g_cnt[NB * NC];
__device__ int   g_jord[NB * NC];         // LPT job order (by count desc)
__device__ float g_cent[NB * NJ * CF];    // [n][c*2+k][d]
__device__ float g_cnorm[NB * NJ];
__device__ float g_D[NB * NJ * HW];       // [n][j][m] = centers[j] . feat[m]
__device__ float g_Kmat[NB * NC * HW * 2];// [n][c][m][k]
__device__ int   g_job;                   // kmeans work queue (reset by k_lists)
__device__ int   g_bar[NB][2];            // sinkhorn chunk barriers (reset by k_camkmat)
__device__ float g_errt[NB * NC][112];    // per-class per-iteration err partials

// packed f32x2 FMA (FFMA2): d = a*b + d, lane-wise on 2 packed floats
#define FMA_F32X2(d, a, b) \
    asm("fma.rn.f32x2 %0, %1, %2, %0;" : "+l"(d) : "l"(a), "l"(b))

// ---- 1. transpose feature (float4 both sides) + per-column partial sumsq ----
__global__ void __launch_bounds__(256) k_transpose(const float* __restrict__ feat) {
    __shared__ float tile[32][129];
    int n = blockIdx.z;
    int d0 = blockIdx.y * 32, m0 = blockIdx.x * 128;
    int t = threadIdx.x;
    #pragma unroll
    for (int i = 0; i < 4; i++) {
        int li = t + i * 256;
        int r = li >> 5, c4 = li & 31;
        float4 v = *(const float4*)&feat[((size_t)(n * CF + d0 + r)) * HW + m0 + c4 * 4];
        tile[r][c4 * 4 + 0] = v.x;
        tile[r][c4 * 4 + 1] = v.y;
        tile[r][c4 * 4 + 2] = v.z;
        tile[r][c4 * 4 + 3] = v.w;
    }
    __syncthreads();
    #pragma unroll
    for (int i = 0; i < 4; i++) {
        int li = t + i * 256;
        int m = li >> 3, d4 = li & 7;
        float4 v;
        v.x = tile[d4 * 4 + 0][m];
        v.y = tile[d4 * 4 + 1][m];
        v.z = tile[d4 * 4 + 2][m];
        v.w = tile[d4 * 4 + 3][m];
        *(float4*)&g_featT[((size_t)(n * HW + m0 + m)) * CF + d0 + d4 * 4] = v;
        float ss = v.x * v.x + v.y * v.y + v.z * v.z + v.w * v.w;
        #pragma unroll
        for (int o = 1; o < 8; o <<= 1) ss += __shfl_xor_sync(0xffffffffu, ss, o);
        if (d4 == 0) g_fpart[blockIdx.y * (NB * HW) + n * HW + m0 + m] = ss;
    }
}

// ---- 2. fused: feature-norm finalize + per-pixel argmax class (full-chip) ----
__global__ void k_prep(const float* __restrict__ cam, const float* __restrict__ label) {
    int idx = blockIdx.x * blockDim.x + threadIdx.x;
    if (idx >= NB * HW) return;
    float s = 0.f;
    #pragma unroll
    for (int k = 0; k < 24; k++) s += g_fpart[k * (NB * HW) + idx];
    g_fnorm[idx] = sqrtf(s);

    int n = idx >> 12, m = idx & (HW - 1);
    const float* cp = cam + (size_t)n * NC * HW + m;
    float best = cp[0];
    int bi = 0;
    #pragma unroll
    for (int c = 1; c < NC; c++) {
        float v = cp[c * HW];
        if (v > best) { best = v; bi = c; }   // first max on ties
    }
    g_pcls[idx] = (label[n * NC + bi] > 0.f) ? bi : -1;
}

// ---- 3. ordered compaction, block per (n,c): thread owns 32-px segment, block scan ----
__global__ void __launch_bounds__(128) k_lists() {
    __shared__ int wt[4];
    int bc = blockIdx.x, n = bc / NC, c = bc % NC, t = threadIdx.x;
    int wid = t >> 5, lane = t & 31;
    if (bc == 0 && t == 0) g_job = 0;    // reset kmeans work queue for this replay
    int4 v[8];
    const int4* pp = (const int4*)(g_pcls + (size_t)n * HW) + t * 8;
    int cnt = 0;
    #pragma unroll
    for (int i = 0; i < 8; i++) {
        v[i] = pp[i];
        cnt += (v[i].x == c) + (v[i].y == c) + (v[i].z == c) + (v[i].w == c);
    }
    int incl = cnt;
    #pragma unroll
    for (int o = 1; o < 32; o <<= 1) {
        int pv = __shfl_up_sync(0xffffffffu, incl, o);
        if (lane >= o) incl += pv;
    }
    if (lane == 31) wt[wid] = incl;
    __syncthreads();
    int woff = 0;
    #pragma unroll
    for (int w = 0; w < 4; w++) woff += (w < wid) ? wt[w] : 0;
    int off = woff + incl - cnt;         // exclusive prefix = my write offset
    int* lst = g_list + (size_t)bc * HW;
    int base = t * 32;
    #pragma unroll
    for (int i = 0; i < 8; i++) {
        if (v[i].x == c) lst[off++] = base + i * 4 + 0;
        if (v[i].y == c) lst[off++] = base + i * 4 + 1;
        if (v[i].z == c) lst[off++] = base + i * 4 + 2;
        if (v[i].w == c) lst[off++] = base + i * 4 + 3;
    }
    if (t == 0) g_cnt[bc] = wt[0] + wt[1] + wt[2] + wt[3];
}

// ---- 3c. LPT job order: rank jobs by pixel count descending (deterministic) ----
__global__ void __launch_bounds__(256) k_order() {
    __shared__ int scnt[NB * NC];
    int t = threadIdx.x;
    if (t < NB * NC) scnt[t] = g_cnt[t];
    __syncthreads();
    if (t < NB * NC) {
        int my = scnt[t];
        int rank = 0;
        #pragma unroll 8
        for (int j = 0; j < NB * NC; j++) {
            int cj = scnt[j];
            rank += (cj > my) || (cj == my && j < t);
        }
        g_jord[rank] = t;
    }
}

// ---- 4. k-means: persistent work queue (LPT order); smem index list; 2-px pipelined ----
#define KW 8   // warps per kmeans block

#define LOADPAIR(VA, VB, HAS, PI) {                                   \
    int _m0 = slst[PI];                                               \
    HAS = (PI + 1 < cnt);                                             \
    int _m1 = HAS ? slst[(PI) + 1] : _m0;                             \
    const float4* _fa = (const float4*)(fbase + (size_t)_m0 * CF) + lane; \
    const float4* _fb = (const float4*)(fbase + (size_t)_m1 * CF) + lane; \
    _Pragma("unroll")                                                 \
    for (int _j = 0; _j < 6; _j++) {                                  \
        VA[_j] = _fa[_j * 32];                                        \
        VB[_j] = _fb[_j * 32];                                        \
    } }

#define DOTPAIR(VA, VB) {                                             \
    d0a = 0.f; d1a = 0.f; d0b = 0.f; d1b = 0.f;                       \
    _Pragma("unroll")                                                 \
    for (int _j = 0; _j < 6; _j++) {                                  \
        float4 _c0 = cen4[lane + _j * 32];                            \
        float4 _c1 = cen4[48 * 4 + lane + _j * 32];                   \
        d0a += VA[_j].x * _c0.x + VA[_j].y * _c0.y                    \
             + VA[_j].z * _c0.z + VA[_j].w * _c0.w;                   \
        d1a += VA[_j].x * _c1.x + VA[_j].y * _c1.y                    \
             + VA[_j].z * _c1.z + VA[_j].w * _c1.w;                   \
        d0b += VB[_j].x * _c0.x + VB[_j].y * _c0.y                    \
             + VB[_j].z * _c0.z + VB[_j].w * _c0.w;                   \
        d1b += VB[_j].x * _c1.x + VB[_j].y * _c1.y                    \
             + VB[_j].z * _c1.z + VB[_j].w * _c1.w;                   \
    } }

#define FINPAIR(VA, VB, HAS, PI) {                                    \
    _Pragma("unroll")                                                 \
    for (int _o = 16; _o; _o >>= 1) {                                 \
        d0a += __shfl_xor_sync(0xffffffffu, d0a, _o);                 \
        d1a += __shfl_xor_sync(0xffffffffu, d1a, _o);                 \
        d0b += __shfl_xor_sync(0xffffffffu, d0b, _o);                 \
        d1b += __shfl_xor_sync(0xffffffffu, d1b, _o);                 \
    }                                                                 \
    int _aa = (d1a * inv1 > d0a * inv0) ? 1 : 0;                      \
    int _ab = (d1b * inv1 > d0b * inv0) ? 1 : 0;                      \
    if (!lane) {                                                      \
        if (iter > 0) mychg += (sprev[PI] != _aa)                     \
                             + (HAS ? (sprev[(PI) + 1] != _ab) : 0);  \
        sprev[PI] = (unsigned char)_aa;                               \
        if (HAS) sprev[(PI) + 1] = (unsigned char)_ab;                \
    }                                                                 \
    float _w0a = _aa ? 0.f : 1.f, _w1a = _aa ? 1.f : 0.f;             \
    float _w0b = 0.f, _w1b = 0.f;                                     \
    if (HAS) { _w0b = _ab ? 0.f : 1.f; _w1b = _ab ? 1.f : 0.f; }      \
    _Pragma("unroll")                                                 \
    for (int _j = 0; _j < 6; _j++) {                                  \
        acc0[_j].x = fmaf(_w0a, VA[_j].x, fmaf(_w0b, VB[_j].x, acc0[_j].x)); \
        acc0[_j].y = fmaf(_w0a, VA[_j].y, fmaf(_w0b, VB[_j].y, acc0[_j].y)); \
        acc0[_j].z = fmaf(_w0a, VA[_j].z, fmaf(_w0b, VB[_j].z, acc0[_j].z)); \
        acc0[_j].w = fmaf(_w0a, VA[_j].w, fmaf(_w0b, VB[_j].w, acc0[_j].w)); \
        acc1[_j].x = fmaf(_w1a, VA[_j].x, fmaf(_w1b, VB[_j].x, acc1[_j].x)); \
        acc1[_j].y = fmaf(_w1a, VA[_j].y, fmaf(_w1b, VB[_j].y, acc1[_j].y)); \
        acc1[_j].z = fmaf(_w1a, VA[_j].z, fmaf(_w1b, VB[_j].z, acc1[_j].z)); \
        acc1[_j].w = fmaf(_w1a, VA[_j].w, fmaf(_w1b, VB[_j].w, acc1[_j].w)); \
    }                                                                 \
    myc0 += (1 - _aa) + (HAS ? (1 - _ab) : 0);                        \
    myc1 += _aa + (HAS ? _ab : 0); }

__global__ void __launch_bounds__(32 * KW) k_kmeans() {
    extern __shared__ float buf[];
    float* cen  = buf;                     // [2][CF]
    float* part = buf + 2 * CF;            // [KW][2][CF]
    int*   slst = (int*)(buf + 2 * CF + KW * 2 * CF);   // [HW] job pixel indices
    float4* cen4 = (float4*)cen;
    __shared__ unsigned char sprev[HW];
    __shared__ int   pcnt[KW][2];
    __shared__ int   pchg[KW];
    __shared__ float inv_s[2];
    __shared__ int   cnts[2], schg, jobS;
    int t = threadIdx.x, wid = t >> 5, lane = t & 31;

    for (;;) {
        if (t == 0) jobS = atomicAdd(&g_job, 1);
        __syncthreads();
        int job = jobS;
        __syncthreads();
        if (job >= NB * NC) return;
        int bc = g_jord[job];                 // LPT: longest jobs first
        int n = bc / NC;
        int cnt = g_cnt[bc];
        float* gc = g_cent + (size_t)bc * 2 * CF;
        if (cnt < 2) {   // reference: centers forced to zero
            for (int i = t; i < 2 * CF; i += 32 * KW) gc[i] = 0.f;
            if (t < 2) g_cnorm[bc * 2 + t] = 0.f;
            __syncthreads();
            continue;
        }
        const int* lst = g_list + (size_t)bc * HW;
        const float* fbase = g_featT + (size_t)n * HW * CF;
        for (int i = t; i < cnt; i += 32 * KW) slst[i] = lst[i];
        __syncthreads();
        int i0 = slst[0], i1 = slst[1];
        for (int d = t; d < CF; d += 32 * KW) {
            cen[d]      = fbase[(size_t)i0 * CF + d];
            cen[CF + d] = fbase[(size_t)i1 * CF + d];
        }
        __syncthreads();

        for (int iter = 0; iter < 10; iter++) {
            if (wid < 2) {   // center inverse norms
                float s = 0.f;
                for (int d = lane; d < CF; d += 32) { float v = cen[wid * CF + d]; s += v * v; }
                #pragma unroll
                for (int o = 16; o; o >>= 1) s += __shfl_xor_sync(0xffffffffu, s, o);
                if (!lane) inv_s[wid] = 1.f / fmaxf(sqrtf(s), 1e-8f);
            }
            __syncthreads();
            float inv0 = inv_s[0], inv1 = inv_s[1];
            float4 acc0[6], acc1[6];
            #pragma unroll
            for (int j = 0; j < 6; j++) {
                acc0[j] = make_float4(0.f, 0.f, 0.f, 0.f);
                acc1[j] = make_float4(0.f, 0.f, 0.f, 0.f);
            }
            int myc0 = 0, myc1 = 0, mychg = 0;

            float4 vax[6], vbx[6], vay[6], vby[6];
            float d0a, d1a, d0b, d1b;
            int hasx = 0, hasy = 0;
            int pi = wid * 2;
            if (pi < cnt) LOADPAIR(vax, vbx, hasx, pi);
            while (pi < cnt) {
                int pj = pi + 2 * KW;
                if (pj < cnt) LOADPAIR(vay, vby, hasy, pj);
                DOTPAIR(vax, vbx);
                FINPAIR(vax, vbx, hasx, pi);
                pi = pj;
                if (pi >= cnt) break;
                pj = pi + 2 * KW;
                if (pj < cnt) LOADPAIR(vax, vbx, hasx, pj);
                DOTPAIR(vay, vby);
                FINPAIR(vay, vby, hasy, pi);
                pi = pj;
            }

            float4* p0 = (float4*)&part[(wid * 2 + 0) * CF];
            float4* p1 = (float4*)&part[(wid * 2 + 1) * CF];
            #pragma unroll
            for (int j = 0; j < 6; j++) {
                p0[lane + j * 32] = acc0[j];
                p1[lane + j * 32] = acc1[j];
            }
            if (!lane) { pcnt[wid][0] = myc0; pcnt[wid][1] = myc1; pchg[wid] = mychg; }
            __syncthreads();
            if (t < 2) {
                int s = 0;
                #pragma unroll
                for (int w2 = 0; w2 < KW; w2++) s += pcnt[w2][t];
                cnts[t] = s;
            }
            if (t == 2) {
                int s = 0;
                #pragma unroll
                for (int w2 = 0; w2 < KW; w2++) s += pchg[w2];
                schg = s;
            }
            __syncthreads();
            float div0 = 1.f / fmaxf((float)cnts[0], 1.f);
            float div1 = 1.f / fmaxf((float)cnts[1], 1.f);
            for (int d = t; d < CF; d += 32 * KW) {
                float s0 = 0.f, s1 = 0.f;
                #pragma unroll
                for (int w2 = 0; w2 < KW; w2++) {
                    s0 += part[(w2 * 2) * CF + d];
                    s1 += part[(w2 * 2 + 1) * CF + d];
                }
                cen[d] = s0 * div0;
                cen[CF + d] = s1 * div1;
            }
            __syncthreads();
            if (iter > 0 && schg == 0) break;   // fixed point
        }
        for (int d = t; d < CF; d += 32 * KW) { gc[d] = cen[d]; gc[CF + d] = cen[CF + d]; }
        if (wid < 2) {
            float s = 0.f;
            for (int d = lane; d < CF; d += 32) { float v = cen[wid * CF + d]; s += v * v; }
            #pragma unroll
            for (int o = 16; o; o >>= 1) s += __shfl_xor_sync(0xffffffffu, s, o);
            if (!lane) g_cnorm[bc * 2 + wid] = sqrtf(s);
        }
        __syncthreads();   // protect smem before next job
    }
}

// ---- 5. GEMM via packed f32x2 FMA: m-tile 128, 128 threads, 256 blocks (full chip) ----
#define GT 48    // k-tile
#define MT 128   // m-tile
__global__ void __launch_bounds__(128) k_gemm(const float* __restrict__ feat) {
    extern __shared__ float sm[];
    float* fS = sm;                                            // [GT][MT]
    unsigned long long* cS2 = (unsigned long long*)(sm + GT * MT);   // [NJ][GT]
    int n = blockIdx.y, m0 = blockIdx.x * MT;
    int t = threadIdx.x;
    int p = t & 63, g = t >> 6;    // p = m-pair, g = j-group (warp-uniform)
    unsigned long long acc[21];
    #pragma unroll
    for (int j = 0; j < 21; j++) acc[j] = 0ull;

    for (int k0 = 0; k0 < CF; k0 += GT) {
        __syncthreads();
        for (int idx = t; idx < GT * (MT / 4); idx += 128) {
            int dd = idx >> 5, c4 = idx & 31;
            float4 v = *(const float4*)&feat[((size_t)(n * CF + k0 + dd)) * HW + m0 + c4 * 4];
            *(float4*)&fS[dd * MT + c4 * 4] = v;
        }
        for (int idx = t; idx < NJ * GT; idx += 128) {
            int j = idx / GT, dd = idx % GT;
            float v = g_cent[((size_t)n * NJ + j) * CF + k0 + dd];
            float2 d2 = make_float2(v, v);
            cS2[j * GT + dd] = *(unsigned long long*)&d2;
        }
        __syncthreads();
        #pragma unroll 4
        for (int dd = 0; dd < GT; dd += 2) {
            unsigned long long a0 = *(const unsigned long long*)&fS[dd * MT + 2 * p];
            unsigned long long a1 = *(const unsigned long long*)&fS[(dd + 1) * MT + 2 * p];
            #pragma unroll
            for (int j = 0; j < 21; j++) {
                ulonglong2 c2 = *(const ulonglong2*)&cS2[(g * 21 + j) * GT + dd];
                FMA_F32X2(acc[j], a0, c2.x);
                FMA_F32X2(acc[j], a1, c2.y);
            }
        }
    }
    #pragma unroll
    for (int j = 0; j < 21; j++) {
        float* dp = g_D + ((size_t)n * NJ + g * 21 + j) * HW + m0;
        *(float2*)&dp[2 * p] = *(float2*)&acc[j];
    }
}

// ---- 6. fused cam + max-normalize + Sinkhorn K, vectorized (regs, no smem staging) ----
__global__ void __launch_bounds__(512) k_camkmat(const float* __restrict__ label,
                                                 float* __restrict__ out) {
    __shared__ float red[512];
    int bc = blockIdx.x, n = bc / NC, c = bc % NC, t = threadIdx.x;
    if (bc == 0 && t < NB * 2) ((int*)g_bar)[t] = 0;   // reset sinkhorn barriers each replay
    int cnt = g_cnt[bc];
    float lab = label[bc];
    float inv_cn0 = 1.f / fmaxf(g_cnorm[n * NJ + 2 * c], 1e-8f);
    float inv_cn1 = 1.f / fmaxf(g_cnorm[n * NJ + 2 * c + 1], 1e-8f);
    float ik0 = 1.f / (g_cnorm[n * NJ + c] + 1e-5f);         // kmat quirk: j = k*21 + c
    float ik1 = 1.f / (g_cnorm[n * NJ + NC + c] + 1e-5f);
    float gate = (cnt >= 2) ? 0.5f * lab : 0.f;
    const float4* D0  = (const float4*)(g_D + ((size_t)n * NJ + 2 * c) * HW);
    const float4* D1  = (const float4*)(g_D + ((size_t)n * NJ + 2 * c + 1) * HW);
    const float4* Dk0 = (const float4*)(g_D + ((size_t)n * NJ + c) * HW);
    const float4* Dk1 = (const float4*)(g_D + ((size_t)n * NJ + NC + c) * HW);
    const float4* FN  = (const float4*)(g_fnorm + n * HW);
    float4* Km4 = (float4*)(g_Kmat + (size_t)bc * HW * 2);
    float4 camv[2];
    float mx = -INFINITY;
    #pragma unroll
    for (int i = 0; i < 2; i++) {
        int f = t + i * 512;                 // float4 index (covers px 4f..4f+3)
        float4 fn = FN[f];
        float4 d0 = D0[f], d1 = D1[f], k0 = Dk0[f], k1 = Dk1[f];
        float4 cv;
        cv.x = (d0.x * inv_cn0 + d1.x * inv_cn1) * gate / fmaxf(fn.x, 1e-8f);
        cv.y = (d0.y * inv_cn0 + d1.y * inv_cn1) * gate / fmaxf(fn.y, 1e-8f);
        cv.z = (d0.z * inv_cn0 + d1.z * inv_cn1) * gate / fmaxf(fn.z, 1e-8f);
        cv.w = (d0.w * inv_cn0 + d1.w * inv_cn1) * gate / fmaxf(fn.w, 1e-8f);
        camv[i] = cv;
        mx = fmaxf(mx, fmaxf(fmaxf(cv.x, cv.y), fmaxf(cv.z, cv.w)));
        float4 ka, kb;   // interleaved [m][k]
        ka.x = __expf((k0.x / (fn.x + 1e-5f) * ik0 - 1.f) * 10.f);
        ka.y = __expf((k1.x / (fn.x + 1e-5f) * ik1 - 1.f) * 10.f);
        ka.z = __expf((k0.y / (fn.y + 1e-5f) * ik0 - 1.f) * 10.f);
        ka.w = __expf((k1.y / (fn.y + 1e-5f) * ik1 - 1.f) * 10.f);
        kb.x = __expf((k0.z / (fn.z + 1e-5f) * ik0 - 1.f) * 10.f);
        kb.y = __expf((k1.z / (fn.z + 1e-5f) * ik1 - 1.f) * 10.f);
        kb.z = __expf((k0.w / (fn.w + 1e-5f) * ik0 - 1.f) * 10.f);
        kb.w = __expf((k1.w / (fn.w + 1e-5f) * ik1 - 1.f) * 10.f);
        Km4[2 * f] = ka;
        Km4[2 * f + 1] = kb;
    }
    red[t] = mx;
    __syncthreads();
    for (int s = 256; s; s >>= 1) { if (t < s) red[t] = fmaxf(red[t], red[t + s]); __syncthreads(); }
    float inv = 1.f / (red[0] + 1e-5f);
    float4* O4 = (float4*)(out + (size_t)bc * HW);
    #pragma unroll
    for (int i = 0; i < 2; i++) {
        int f = t + i * 512;
        float4 cv = camv[i];
        cv.x *= inv; cv.y *= inv; cv.z *= inv; cv.w *= inv;
        O4[f] = cv;
    }
}

// ---- 7. Sinkhorn (+ fused T output): block per (n,c), r in registers, cv trajectory in
//        smem, speculative chunks + one cross-block barrier per chunk. Final r_T rolled
//        forward from cv[T-1] and written as T = (r*cv)*K directly ----
__global__ void __launch_bounds__(256) k_sinkhorn(float* __restrict__ Tout) {
    __shared__ float cvh[112][2];     // cv trajectory (after each body)
    __shared__ float partE[8], partA[8], partB[8];
    __shared__ int   shT;
    int bc = blockIdx.x, n = bc / NC;
    int t = threadIdx.x, lane = t & 31, wid = t >> 5;
    const float u = 1.f / (float)HW, v = 0.5f;
    const float4* Km4 = (const float4*)(g_Kmat + (size_t)bc * HW * 2);
    float rp[16];                      // current r (16 px per thread)
    #pragma unroll
    for (int j = 0; j < 16; j++) rp[j] = 1.f;
    float cv0 = 1.f, cv1 = 1.f;
    int T = -1;

    for (int chunk = 0; chunk < 100; chunk += SCH) {
        int cend = chunk + SCH; if (cend > 100) cend = 100;
        for (int it = chunk; it < cend; it++) {
            float errp = 0.f, s0 = 0.f, s1 = 0.f;
            #pragma unroll
            for (int st = 0; st < 8; st++) {
                float4 kk = Km4[t + st * 256];         // px pair (2i2, 2i2+1)
                float rn0 = u / (kk.x * cv0 + kk.y * cv1);
                float rn1 = u / (kk.z * cv0 + kk.w * cv1);
                errp += fabsf(rn0 - rp[2 * st]) + fabsf(rn1 - rp[2 * st + 1]);
                rp[2 * st] = rn0; rp[2 * st + 1] = rn1;
                s0 += kk.x * rn0 + kk.z * rn1;
                s1 += kk.y * rn0 + kk.w * rn1;
            }
            #pragma unroll
            for (int o = 16; o; o >>= 1) {
                errp += __shfl_xor_sync(0xffffffffu, errp, o);
                s0   += __shfl_xor_sync(0xffffffffu, s0, o);
                s1   += __shfl_xor_sync(0xffffffffu, s1, o);
            }
            if (!lane) { partE[wid] = errp; partA[wid] = s0; partB[wid] = s1; }
            __syncthreads();
            if (t == 0) {
                float e = 0.f, a = 0.f, b = 0.f;
                #pragma unroll
                for (int w = 0; w < 8; w++) { e += partE[w]; a += partA[w]; b += partB[w]; }
                g_errt[bc][it] = e;
                cvh[it][0] = v / a;
                cvh[it][1] = v / b;
            }
            __syncthreads();
            cv0 = cvh[it][0]; cv1 = cvh[it][1];
        }
        // cross-block barrier (21 class-blocks of this n), monotonic counter
        if (t == 0) {
            __threadfence();
            atomicAdd(&g_bar[n][0], 1);
            int target = NC * (chunk / SCH + 1);
            while (atomicAdd(&g_bar[n][0], 0) < target) { }
            __threadfence();
            int Tf = -1;
            for (int i2 = chunk; i2 < cend && Tf < 0; i2++) {
                float es = 0.f;
                for (int cc = 0; cc < NC; cc++) es += g_errt[n * NC + cc][i2];
                if (es / (float)(NC * HW) < 0.01f) Tf = i2;
            }
            shT = Tf;
        }
        __syncthreads();
        if (shT >= 0) { T = shT; break; }
    }
    if (T < 0) T = 99;
    // rollforward r_T from cv[T-1] (identical expression) and emit T directly
    float c0p = (T == 0) ? 1.f : cvh[T - 1][0];
    float c1p = (T == 0) ? 1.f : cvh[T - 1][1];
    float cvT0 = cvh[T][0], cvT1 = cvh[T][1];
    float2* T0 = (float2*)(Tout + (size_t)bc * 2 * HW);   // [n][c][k=0][m]
    float2* T1 = T0 + HW / 2;                             // [n][c][k=1][m]
    #pragma unroll
    for (int st = 0; st < 8; st++) {
        int f = t + st * 256;
        float4 kk = Km4[f];          // pixels 2f, 2f+1
        float r0 = u / (kk.x * c0p + kk.y * c1p);
        float r1 = u / (kk.z * c0p + kk.w * c1p);
        float2 o0, o1;
        o0.x = r0 * cvT0 * kk.x;  o0.y = r1 * cvT0 * kk.z;
        o1.x = r0 * cvT1 * kk.y;  o1.y = r1 * cvT1 * kk.w;
        T0[f] = o0;
        T1[f] = o1;
    }
}

// ---------------- launcher ----------------
extern "C" void kernel_launch(void* const* d_in, const int* in_sizes, int n_in,
                              void* d_out, int out_size) {
    const float* norm_cam = (const float*)d_in[0];   // [8,21,64,64]
    const float* label    = (const float*)d_in[1];   // [8,21,1,1]
    const float* feature  = (const float*)d_in[2];   // [8,768,64,64]
    float* out  = (float*)d_out;                     // [8,21,64,64]
    float* Tout = out + NB * NC * HW;                // [8,21,2,64,64]

    const int KMEANS_SMEM = (2 * CF + KW * 2 * CF) * sizeof(float) + HW * 4;  // 71680 B
    const int GEMM_SMEM   = GT * MT * 4 + NJ * GT * 8;                        // 40704 B
    cudaFuncSetAttribute(k_kmeans, cudaFuncAttributeMaxDynamicSharedMemorySize, KMEANS_SMEM);
    cudaFuncSetAttribute(k_gemm,   cudaFuncAttributeMaxDynamicSharedMemorySize, GEMM_SMEM);

    k_transpose<<<dim3(HW / 128, CF / 32, NB), 256>>>(feature);
    k_prep    <<<(NB * HW + 255) / 256, 256>>>(norm_cam, label);
    k_lists   <<<NB * NC, 128>>>();
    k_order   <<<1, 256>>>();
    k_kmeans  <<<148, 32 * KW, KMEANS_SMEM>>>();
    k_gemm    <<<dim3(HW / MT, NB), 128, GEMM_SMEM>>>(feature);
    k_camkmat <<<NB * NC, 512>>>(label, out);
    k_sinkhorn<<<NB * NC, 256>>>(Tout);
}